// round 13
// baseline (speedup 1.0000x reference)
#include <cuda_runtime.h>
#include <cuda_bf16.h>
#include <cuda_fp16.h>
#include <math.h>
#include <stdint.h>

// ---------------------------------------------------------------------------
// GPT forward: B=2, T=1024, C=1024, H=16, hd=64, F=4096, V=32000, L=8
// Layer GEMMs + attention: fp16 2-term. Head: 1-term fp16. BK=64.
// R13: hoisted-ldsm mainloop (volatile-asm order = SASS order), term-major
// mma schedule (RAW distance 8), dead K/V lo-plane stores skipped.
// ---------------------------------------------------------------------------

#define BT 2048
#define CDIM 1024
#define FDIM 4096
#define VDIM 32000
#define NH 16
#define HD 64
#define TLEN 1024
#define NLAYER 8
#define C3 (3 * 1024)

typedef __nv_bfloat16 bf16;

// ------------------------- scratch ------------------------------------------
__device__ __align__(128) float g_x[BT * CDIM];
__device__ __align__(128) __half g_ah[BT * CDIM], g_al[BT * CDIM];
__device__ __align__(128) __half g_qkvh[BT * C3], g_qkvl[BT * C3];
__device__ __align__(128) __half g_fh[BT * FDIM], g_fl[BT * FDIM];
__device__ __align__(128) __half g_wqkv16[NLAYER * C3 * CDIM];
__device__ __align__(128) float g_bqkv[NLAYER * C3];
__device__ __align__(128) __half g_w116[NLAYER * CDIM * FDIM];
__device__ __align__(128) __half g_w216[NLAYER * FDIM * CDIM];
__device__ __align__(128) __half g_hw16[(size_t)VDIM * CDIM];

// ------------------------- PTX helpers --------------------------------------
__device__ __forceinline__ uint32_t smem_u32(const void* p) {
    uint32_t a;
    asm("{ .reg .u64 t; cvta.to.shared.u64 t, %1; cvt.u32.u64 %0, t; }"
        : "=r"(a) : "l"(p));
    return a;
}
__device__ __forceinline__ void cp16(uint32_t dst, const void* src) {
    asm volatile("cp.async.cg.shared.global [%0], [%1], 16;" :: "r"(dst), "l"(src));
}
__device__ __forceinline__ void cp_commit() {
    asm volatile("cp.async.commit_group;" ::: "memory");
}
__device__ __forceinline__ void cp_wait0() {
    asm volatile("cp.async.wait_group 0;" ::: "memory");
}
__device__ __forceinline__ void ldsm4(uint32_t (&r)[4], uint32_t a) {
    asm volatile("ldmatrix.sync.aligned.m8n8.x4.shared.b16 {%0,%1,%2,%3}, [%4];"
        : "=r"(r[0]), "=r"(r[1]), "=r"(r[2]), "=r"(r[3]) : "r"(a));
}
__device__ __forceinline__ void ldsm4t(uint32_t (&r)[4], uint32_t a) {
    asm volatile("ldmatrix.sync.aligned.m8n8.x4.trans.shared.b16 {%0,%1,%2,%3}, [%4];"
        : "=r"(r[0]), "=r"(r[1]), "=r"(r[2]), "=r"(r[3]) : "r"(a));
}
__device__ __forceinline__ void mma16816h(float (&c)[4], const uint32_t (&a)[4],
                                          uint32_t b0, uint32_t b1) {
    asm volatile("mma.sync.aligned.m16n8k16.row.col.f32.f16.f16.f32 "
        "{%0,%1,%2,%3}, {%4,%5,%6,%7}, {%8,%9}, {%0,%1,%2,%3};"
        : "+f"(c[0]), "+f"(c[1]), "+f"(c[2]), "+f"(c[3])
        : "r"(a[0]), "r"(a[1]), "r"(a[2]), "r"(a[3]), "r"(b0), "r"(b1));
}
__device__ __forceinline__ void split2h(float a, float b, uint32_t& hp, uint32_t& lp) {
    __half ha = __float2half_rn(a), hb = __float2half_rn(b);
    __half la = __float2half_rn(a - __half2float(ha));
    __half lb = __float2half_rn(b - __half2float(hb));
    hp = (uint32_t)__half_as_ushort(ha) | ((uint32_t)__half_as_ushort(hb) << 16);
    lp = (uint32_t)__half_as_ushort(la) | ((uint32_t)__half_as_ushort(lb) << 16);
}

#define TSTR64 144
#define TILE64 (128 * TSTR64)          // 18432
#define STAGE64 (3 * TILE64)           // 55296
#define GEMM64_SMEM (2 * STAGE64)      // 110592
#define STAGE1_B (2 * TILE64)          // 36864
#define GEMM1_SMEM (2 * STAGE1_B)      // 73728

// ---------------------------------------------------------------------------
// fp16 2-term 128x128 GEMM, BK=64: C = (Ah+Al)@Bh^T.
// QLO: when OSPLIT, store lo-plane only for col < 1024 (QKV: K/V lo unused).
// ---------------------------------------------------------------------------
template<int GELU, int OSPLIT, int QLO>
__global__ __launch_bounds__(256, 2) void hmma_gemm_h2(
    const __half* __restrict__ Ah, const __half* __restrict__ Al,
    const __half* __restrict__ Bh,
    const float* __restrict__ bias, const float* __restrict__ resid,
    float* __restrict__ C, __half* __restrict__ Oh, __half* __restrict__ Ol,
    int M, int N, int K)
{
    extern __shared__ char sm[];
    const uint32_t sb = smem_u32(sm);
    const int tid = threadIdx.x;
    const int wid = tid >> 5;
    const int lid = tid & 31;
    const int bn = blockIdx.x * 128;
    const int bm = blockIdx.y * 128;
    const int wm = (wid & 3) * 32;
    const int wn = (wid >> 2) * 64;

    float acc[2][8][4];
    #pragma unroll
    for (int i = 0; i < 2; i++)
        #pragma unroll
        for (int j = 0; j < 8; j++)
            #pragma unroll
            for (int t = 0; t < 4; t++) acc[i][j][t] = 0.f;

    const uint32_t aoff = (uint32_t)((lid & 15) * TSTR64 + (lid >> 4) * 16);
    const uint32_t boff = (uint32_t)(((lid & 7) + (lid >> 4) * 8) * TSTR64
                                     + ((lid >> 3) & 1) * 16);
    const int nch = K >> 6;

    auto load_stage = [&](int ch, int s) {
        const int k0 = ch << 6;
        const uint32_t sbase = sb + s * STAGE64;
        #pragma unroll
        for (int u = 0; u < 4; u++) {
            int f = tid + u * 256;
            int r = f >> 3, c = f & 7;
            uint32_t so = (uint32_t)(r * TSTR64 + c * 16);
            size_t ga = (size_t)(bm + r) * K + k0 + c * 8;
            size_t gb = (size_t)(bn + r) * K + k0 + c * 8;
            cp16(sbase + 0 * TILE64 + so, Ah + ga);
            cp16(sbase + 1 * TILE64 + so, Al + ga);
            cp16(sbase + 2 * TILE64 + so, Bh + gb);
        }
    };

    load_stage(0, 0);
    cp_commit();

    for (int ch = 0; ch < nch; ch++) {
        const int s = ch & 1;
        cp_wait0();
        __syncthreads();
        if (ch + 1 < nch) {
            load_stage(ch + 1, s ^ 1);
            cp_commit();
        }

        const uint32_t stg = sb + s * STAGE64;
        #pragma unroll
        for (int ks = 0; ks < 4; ks++) {
            // ---- hoist ALL ldsm for this ks (volatile order = SASS order) ----
            uint32_t ah_[2][4], al_[2][4], bh_[4][4];
            #pragma unroll
            for (int mb = 0; mb < 2; mb++) {
                uint32_t abase = stg + (uint32_t)((wm + mb * 16) * TSTR64)
                                 + aoff + ks * 32;
                ldsm4(ah_[mb], abase);
                ldsm4(al_[mb], abase + TILE64);
            }
            #pragma unroll
            for (int nb2 = 0; nb2 < 4; nb2++) {
                uint32_t bbase = stg + 2 * TILE64
                                 + (uint32_t)((wn + nb2 * 16) * TSTR64)
                                 + boff + ks * 32;
                ldsm4(bh_[nb2], bbase);
            }
            // ---- 16 back-to-back mmas, term-major (acc RAW distance = 8) ----
            #pragma unroll
            for (int nb2 = 0; nb2 < 4; nb2++)
                #pragma unroll
                for (int mb = 0; mb < 2; mb++) {
                    mma16816h(acc[mb][nb2 * 2 + 0], ah_[mb], bh_[nb2][0], bh_[nb2][1]);
                    mma16816h(acc[mb][nb2 * 2 + 1], ah_[mb], bh_[nb2][2], bh_[nb2][3]);
                }
            #pragma unroll
            for (int nb2 = 0; nb2 < 4; nb2++)
                #pragma unroll
                for (int mb = 0; mb < 2; mb++) {
                    mma16816h(acc[mb][nb2 * 2 + 0], al_[mb], bh_[nb2][0], bh_[nb2][1]);
                    mma16816h(acc[mb][nb2 * 2 + 1], al_[mb], bh_[nb2][2], bh_[nb2][3]);
                }
        }
    }

    const int er = bm + wm + (lid >> 2);
    const int ec = bn + wn + (lid & 3) * 2;
    #pragma unroll
    for (int mb = 0; mb < 2; mb++) {
        #pragma unroll
        for (int half = 0; half < 2; half++) {
            const int row = er + mb * 16 + half * 8;
            #pragma unroll
            for (int nb = 0; nb < 8; nb++) {
                const int col = ec + nb * 8;
                float v0 = acc[mb][nb][half * 2 + 0];
                float v1 = acc[mb][nb][half * 2 + 1];
                if (bias) { v0 += bias[col]; v1 += bias[col + 1]; }
                if (GELU) {
                    v0 = 0.5f * v0 * (1.0f + erff(v0 * 0.70710678118654752f));
                    v1 = 0.5f * v1 * (1.0f + erff(v1 * 0.70710678118654752f));
                }
                if (OSPLIT) {
                    uint32_t hp, lp;
                    split2h(v0, v1, hp, lp);
                    *reinterpret_cast<uint32_t*>(Oh + (size_t)row * N + col) = hp;
                    if (!QLO || col < 1024)
                        *reinterpret_cast<uint32_t*>(Ol + (size_t)row * N + col) = lp;
                } else {
                    if (resid) {
                        const float* rr = resid + (size_t)row * N;
                        v0 += rr[col]; v1 += rr[col + 1];
                    }
                    *reinterpret_cast<float2*>(C + (size_t)row * N + col) =
                        make_float2(v0, v1);
                }
            }
        }
    }
}

// ---------------------------------------------------------------------------
// fp16 1-term 128x128 GEMM, BK=64 (head): C = Ah@Bh^T (fp32 out).
// ---------------------------------------------------------------------------
__global__ __launch_bounds__(256, 2) void hmma_gemm_h1(
    const __half* __restrict__ Ah, const __half* __restrict__ Bh,
    float* __restrict__ C, int M, int N, int K)
{
    extern __shared__ char sm[];
    const uint32_t sb = smem_u32(sm);
    const int tid = threadIdx.x;
    const int wid = tid >> 5;
    const int lid = tid & 31;
    const int bn = blockIdx.x * 128;
    const int bm = blockIdx.y * 128;
    const int wm = (wid & 3) * 32;
    const int wn = (wid >> 2) * 64;

    float acc[2][8][4];
    #pragma unroll
    for (int i = 0; i < 2; i++)
        #pragma unroll
        for (int j = 0; j < 8; j++)
            #pragma unroll
            for (int t = 0; t < 4; t++) acc[i][j][t] = 0.f;

    const uint32_t aoff = (uint32_t)((lid & 15) * TSTR64 + (lid >> 4) * 16);
    const uint32_t boff = (uint32_t)(((lid & 7) + (lid >> 4) * 8) * TSTR64
                                     + ((lid >> 3) & 1) * 16);
    const int nch = K >> 6;

    auto load_stage = [&](int ch, int s) {
        const int k0 = ch << 6;
        const uint32_t sbase = sb + s * STAGE1_B;
        #pragma unroll
        for (int u = 0; u < 4; u++) {
            int f = tid + u * 256;
            int r = f >> 3, c = f & 7;
            uint32_t so = (uint32_t)(r * TSTR64 + c * 16);
            size_t ga = (size_t)(bm + r) * K + k0 + c * 8;
            size_t gb = (size_t)(bn + r) * K + k0 + c * 8;
            cp16(sbase + 0 * TILE64 + so, Ah + ga);
            cp16(sbase + 1 * TILE64 + so, Bh + gb);
        }
    };

    load_stage(0, 0);
    cp_commit();

    for (int ch = 0; ch < nch; ch++) {
        const int s = ch & 1;
        cp_wait0();
        __syncthreads();
        if (ch + 1 < nch) {
            load_stage(ch + 1, s ^ 1);
            cp_commit();
        }

        const uint32_t stg = sb + s * STAGE1_B;
        #pragma unroll
        for (int ks = 0; ks < 4; ks++) {
            uint32_t ah_[2][4], bh_[4][4];
            #pragma unroll
            for (int mb = 0; mb < 2; mb++) {
                uint32_t abase = stg + (uint32_t)((wm + mb * 16) * TSTR64)
                                 + aoff + ks * 32;
                ldsm4(ah_[mb], abase);
            }
            #pragma unroll
            for (int nb2 = 0; nb2 < 4; nb2++) {
                uint32_t bbase = stg + TILE64
                                 + (uint32_t)((wn + nb2 * 16) * TSTR64)
                                 + boff + ks * 32;
                ldsm4(bh_[nb2], bbase);
            }
            #pragma unroll
            for (int nb2 = 0; nb2 < 4; nb2++)
                #pragma unroll
                for (int mb = 0; mb < 2; mb++) {
                    mma16816h(acc[mb][nb2 * 2 + 0], ah_[mb], bh_[nb2][0], bh_[nb2][1]);
                    mma16816h(acc[mb][nb2 * 2 + 1], ah_[mb], bh_[nb2][2], bh_[nb2][3]);
                }
        }
    }

    const int er = bm + wm + (lid >> 2);
    const int ec = bn + wn + (lid & 3) * 2;
    #pragma unroll
    for (int mb = 0; mb < 2; mb++) {
        #pragma unroll
        for (int half = 0; half < 2; half++) {
            const int row = er + mb * 16 + half * 8;
            #pragma unroll
            for (int nb = 0; nb < 8; nb++) {
                const int col = ec + nb * 8;
                *reinterpret_cast<float2*>(C + (size_t)row * N + col) =
                    make_float2(acc[mb][nb][half * 2 + 0],
                                acc[mb][nb][half * 2 + 1]);
            }
        }
    }
}

// ---------------------------------------------------------------------------
// Flash attention, fp16: Q 2-term, K/V single fp16. (unchanged)
// ---------------------------------------------------------------------------
#define XSTR 3072
#define FSTR 144
#define FKTILE (64 * FSTR)
#define FA_STAGE (2 * FKTILE)
#define FA_SMEM  (2 * FA_STAGE)

__global__ __launch_bounds__(256) void flash_attn(
    const __half* __restrict__ qkvh, const __half* __restrict__ qkvl,
    float* __restrict__ x)
{
    extern __shared__ char sm[];
    const uint32_t sb = smem_u32(sm);
    const int tid = threadIdx.x;
    const int wid = tid >> 5;
    const int lid = tid & 31;
    const int qt = blockIdx.x;
    const int bh = blockIdx.y;
    const int b = bh >> 4, h = bh & 15;
    const size_t qrow0 = (size_t)b * TLEN + qt * 128;
    const size_t krow0 = (size_t)b * TLEN;
    const int hoff = h * HD;
    const int wm = wid * 16;

    auto load_kv = [&](int ssn, int s) {
        const size_t srow0 = krow0 + (size_t)ssn * 64;
        const uint32_t stb = sb + s * FA_STAGE;
        #pragma unroll
        for (int u = 0; u < 4; u++) {
            int f = tid + u * 256;
            int buf = f >> 9, r = (f >> 3) & 63, c = f & 7;
            int coloff = 1024 + (buf << 10) + hoff + c * 8;
            cp16(stb + buf * FKTILE + r * FSTR + c * 16,
                 qkvh + (srow0 + r) * XSTR + coloff);
        }
    };

    #pragma unroll
    for (int u = 0; u < 8; u++) {
        int f = tid + u * 256;
        int buf = f >> 10, r = (f >> 3) & 127, c = f & 7;
        const __half* src = buf ? qkvl : qkvh;
        cp16(sb + buf * 18432 + r * FSTR + c * 16,
             src + (qrow0 + r) * XSTR + hoff + c * 8);
    }
    cp_commit();
    cp_wait0();
    __syncthreads();

    uint32_t qfh[4][4], qfl[4][4];
    {
        uint32_t qaddr = sb + (uint32_t)((wm + (lid & 15)) * FSTR + (lid >> 4) * 16);
        #pragma unroll
        for (int ks = 0; ks < 4; ks++) {
            ldsm4(qfh[ks], qaddr + ks * 32);
            ldsm4(qfl[ks], qaddr + 18432 + ks * 32);
        }
    }
    __syncthreads();

    load_kv(0, 0);
    cp_commit();

    float oacc[8][4];
    #pragma unroll
    for (int i = 0; i < 8; i++)
        #pragma unroll
        for (int j = 0; j < 4; j++) oacc[i][j] = 0.f;
    float m0 = -1e30f, m1 = -1e30f, l0 = 0.f, l1 = 0.f;

    const int r_lo = lid >> 2;
    const int cb = (lid & 3) * 2;
    const uint32_t kboff = (uint32_t)(((lid & 7) + ((lid >> 4) << 3)) * FSTR
                                      + (((lid >> 3) & 1) << 4));
    const uint32_t vboff = (uint32_t)((((lid >> 3) & 1) * 8 + (lid & 7)) * FSTR
                                      + ((lid >> 4) << 4));
    const int ssmax = 2 * qt + 1;

    for (int ss = 0; ss <= ssmax; ss++) {
        const int s = ss & 1;
        cp_wait0();
        __syncthreads();
        if (ss < ssmax) {
            load_kv(ss + 1, s ^ 1);
            cp_commit();
        }

        const bool active = (ss * 64) <= (qt * 128 + wm + 15);
        if (active) {
            const uint32_t stg = sb + s * FA_STAGE;
            float sacc[8][4];
            #pragma unroll
            for (int i = 0; i < 8; i++)
                #pragma unroll
                for (int j = 0; j < 4; j++) sacc[i][j] = 0.f;
            #pragma unroll
            for (int nb2 = 0; nb2 < 4; nb2++) {
                #pragma unroll
                for (int ks = 0; ks < 4; ks++) {
                    uint32_t bhreg[4];
                    uint32_t a_ = stg + kboff + (uint32_t)(nb2 * 16 * FSTR) + ks * 32;
                    ldsm4(bhreg, a_);
                    mma16816h(sacc[nb2 * 2 + 0], qfh[ks], bhreg[0], bhreg[1]);
                    mma16816h(sacc[nb2 * 2 + 1], qfh[ks], bhreg[2], bhreg[3]);
                    mma16816h(sacc[nb2 * 2 + 0], qfl[ks], bhreg[0], bhreg[1]);
                    mma16816h(sacc[nb2 * 2 + 1], qfl[ks], bhreg[2], bhreg[3]);
                }
            }
            const int t0g = qt * 128 + wm + r_lo;
            #pragma unroll
            for (int nb = 0; nb < 8; nb++) {
                #pragma unroll
                for (int j = 0; j < 4; j++) {
                    float v = sacc[nb][j] * 0.125f;
                    int s_g = ss * 64 + nb * 8 + cb + (j & 1);
                    int t_g = t0g + (j >> 1) * 8;
                    sacc[nb][j] = (s_g > t_g) ? -1e30f : v;
                }
            }
            float mx0 = -1e30f, mx1 = -1e30f;
            #pragma unroll
            for (int nb = 0; nb < 8; nb++) {
                mx0 = fmaxf(mx0, fmaxf(sacc[nb][0], sacc[nb][1]));
                mx1 = fmaxf(mx1, fmaxf(sacc[nb][2], sacc[nb][3]));
            }
            mx0 = fmaxf(mx0, __shfl_xor_sync(0xffffffffu, mx0, 1));
            mx0 = fmaxf(mx0, __shfl_xor_sync(0xffffffffu, mx0, 2));
            mx1 = fmaxf(mx1, __shfl_xor_sync(0xffffffffu, mx1, 1));
            mx1 = fmaxf(mx1, __shfl_xor_sync(0xffffffffu, mx1, 2));
            float nm0 = fmaxf(m0, mx0), nm1 = fmaxf(m1, mx1);
            float f0 = __expf(m0 - nm0), f1 = __expf(m1 - nm1);
            m0 = nm0; m1 = nm1;
            float rs0 = 0.f, rs1 = 0.f;
            #pragma unroll
            for (int nb = 0; nb < 8; nb++) {
                float p0 = __expf(sacc[nb][0] - nm0);
                float p1 = __expf(sacc[nb][1] - nm0);
                float p2 = __expf(sacc[nb][2] - nm1);
                float p3 = __expf(sacc[nb][3] - nm1);
                sacc[nb][0] = p0; sacc[nb][1] = p1;
                sacc[nb][2] = p2; sacc[nb][3] = p3;
                rs0 += p0 + p1; rs1 += p2 + p3;
            }
            rs0 += __shfl_xor_sync(0xffffffffu, rs0, 1);
            rs0 += __shfl_xor_sync(0xffffffffu, rs0, 2);
            rs1 += __shfl_xor_sync(0xffffffffu, rs1, 1);
            rs1 += __shfl_xor_sync(0xffffffffu, rs1, 2);
            l0 = l0 * f0 + rs0;
            l1 = l1 * f1 + rs1;
            #pragma unroll
            for (int i = 0; i < 8; i++) {
                oacc[i][0] *= f0; oacc[i][1] *= f0;
                oacc[i][2] *= f1; oacc[i][3] *= f1;
            }
            #pragma unroll
            for (int kk = 0; kk < 4; kk++) {
                uint32_t ph[4], pl[4];
                split2h(sacc[2 * kk][0], sacc[2 * kk][1], ph[0], pl[0]);
                split2h(sacc[2 * kk][2], sacc[2 * kk][3], ph[1], pl[1]);
                split2h(sacc[2 * kk + 1][0], sacc[2 * kk + 1][1], ph[2], pl[2]);
                split2h(sacc[2 * kk + 1][2], sacc[2 * kk + 1][3], ph[3], pl[3]);
                #pragma unroll
                for (int db2 = 0; db2 < 4; db2++) {
                    uint32_t vhreg[4];
                    uint32_t va = stg + FKTILE
                                  + (uint32_t)(kk * 16 * FSTR) + vboff
                                  + (uint32_t)(db2 * 32);
                    ldsm4t(vhreg, va);
                    mma16816h(oacc[db2 * 2 + 0], ph, vhreg[0], vhreg[1]);
                    mma16816h(oacc[db2 * 2 + 1], ph, vhreg[2], vhreg[3]);
                    mma16816h(oacc[db2 * 2 + 0], pl, vhreg[0], vhreg[1]);
                    mma16816h(oacc[db2 * 2 + 1], pl, vhreg[2], vhreg[3]);
                }
            }
        }
        __syncthreads();
    }

    const float inv0 = 1.0f / l0;
    const float inv1 = 1.0f / l1;
    const size_t tr0 = qrow0 + wm + r_lo;
    const size_t tr1 = tr0 + 8;
    #pragma unroll
    for (int db = 0; db < 8; db++) {
        const int col = hoff + db * 8 + cb;
        x[tr0 * CDIM + col]     += oacc[db][0] * inv0;
        x[tr0 * CDIM + col + 1] += oacc[db][1] * inv0;
        x[tr1 * CDIM + col]     += oacc[db][2] * inv1;
        x[tr1 * CDIM + col + 1] += oacc[db][3] * inv1;
    }
}

// ---------------------------------------------------------------------------
// Weight prep
// ---------------------------------------------------------------------------
__global__ __launch_bounds__(256) void transpose_f16_kernel(
    const float* __restrict__ W, __half* __restrict__ T, int K, int N,
    size_t src_lstride, size_t dst_lstride)
{
    __shared__ float ts[32][33];
    W += src_lstride * blockIdx.z;
    T += dst_lstride * blockIdx.z;
    const int n0 = blockIdx.x * 32, k0 = blockIdx.y * 32;
    const int tx = threadIdx.x & 31, ty = threadIdx.x >> 5;

    #pragma unroll
    for (int rr = 0; rr < 32; rr += 8)
        ts[ty + rr][tx] = W[(size_t)(k0 + ty + rr) * N + n0 + tx];
    __syncthreads();
    #pragma unroll
    for (int rr = 0; rr < 32; rr += 8)
        T[(size_t)(n0 + ty + rr) * K + k0 + tx] = __float2half_rn(ts[tx][ty + rr]);
}

__global__ __launch_bounds__(256) void transpose_qkv16_kernel(
    const float* __restrict__ wq, const float* __restrict__ wk,
    const float* __restrict__ wv, __half* __restrict__ T)
{
    __shared__ float ts[32][33];
    const int z = blockIdx.z;
    const int l = z / 3, sec = z % 3;
    const size_t CC = (size_t)CDIM * CDIM;
    const float* W = ((sec == 0) ? wq : (sec == 1) ? wk : wv) + (size_t)l * CC;
    __half* t = T + (size_t)l * 3 * CC + (size_t)sec * CC;
    const int n0 = blockIdx.x * 32, k0 = blockIdx.y * 32;
    const int tx = threadIdx.x & 31, ty = threadIdx.x >> 5;

    #pragma unroll
    for (int rr = 0; rr < 32; rr += 8)
        ts[ty + rr][tx] = W[(size_t)(k0 + ty + rr) * CDIM + n0 + tx];
    __syncthreads();
    #pragma unroll
    for (int rr = 0; rr < 32; rr += 8)
        t[(size_t)(n0 + ty + rr) * CDIM + k0 + tx] = __float2half_rn(ts[tx][ty + rr]);
}

// ---------------------------------------------------------------------------
// Embedding + QKV bias packing (fused)
// ---------------------------------------------------------------------------
#define EMBED_BLOCKS (BT * CDIM / 256)
#define PACK_BLOCKS  ((NLAYER * C3 + 255) / 256)

__global__ __launch_bounds__(256) void embed_pack_kernel(
    const int* __restrict__ idx, const float* __restrict__ tok,
    const float* __restrict__ pos, float* __restrict__ x,
    const float* __restrict__ bq, const float* __restrict__ bk,
    const float* __restrict__ bv, float* __restrict__ bqkv)
{
    if (blockIdx.x < EMBED_BLOCKS) {
        int i = blockIdx.x * 256 + threadIdx.x;
        int n = i >> 10;
        int c = i & (CDIM - 1);
        int t = n & (TLEN - 1);
        x[i] = tok[(size_t)idx[n] * CDIM + c] + pos[(size_t)t * CDIM + c];
    } else {
        int i = (blockIdx.x - EMBED_BLOCKS) * 256 + threadIdx.x;
        if (i < NLAYER * C3) {
            int l = i / C3, rem = i % C3, sec = rem >> 10, c = rem & 1023;
            const float* src = (sec == 0) ? bq : (sec == 1) ? bk : bv;
            bqkv[i] = src[l * CDIM + c];
        }
    }
}

// ---------------------------------------------------------------------------
// LayerNorm -> fp16 split pair
// ---------------------------------------------------------------------------
__global__ __launch_bounds__(256) void layernorm_split16_kernel(
    const float* __restrict__ x, const float* __restrict__ w,
    const float* __restrict__ b, __half* __restrict__ oh, __half* __restrict__ ol)
{
    __shared__ float2 sh[8];
    const size_t row = blockIdx.x;
    const int tid = threadIdx.x;
    const float* xr = x + row * CDIM;

    float4 v = *reinterpret_cast<const float4*>(&xr[tid * 4]);
    float s  = v.x + v.y + v.z + v.w;
    float ss = v.x * v.x + v.y * v.y + v.z * v.z + v.w * v.w;
    #pragma unroll
    for (int o = 16; o > 0; o >>= 1) {
        s  += __shfl_xor_sync(0xffffffffu, s,  o);
        ss += __shfl_xor_sync(0xffffffffu, ss, o);
    }
    if ((tid & 31) == 0) sh[tid >> 5] = make_float2(s, ss);
    __syncthreads();
    float ts = 0.f, tss = 0.f;
    #pragma unroll
    for (int i = 0; i < 8; i++) { ts += sh[i].x; tss += sh[i].y; }
    const float mu  = ts * (1.0f / CDIM);
    const float var = tss * (1.0f / CDIM) - mu * mu;
    const float rstd = rsqrtf(var + 1e-5f);

    float4 wv = *reinterpret_cast<const float4*>(&w[tid * 4]);
    float4 bv = *reinterpret_cast<const float4*>(&b[tid * 4]);
    float o0 = (v.x - mu) * rstd * wv.x + bv.x;
    float o1 = (v.y - mu) * rstd * wv.y + bv.y;
    float o2 = (v.z - mu) * rstd * wv.z + bv.z;
    float o3 = (v.w - mu) * rstd * wv.w + bv.w;
    uint32_t h0, l0p, h1, l1p;
    split2h(o0, o1, h0, l0p);
    split2h(o2, o3, h1, l1p);
    uint32_t* ohp = reinterpret_cast<uint32_t*>(oh + row * CDIM + tid * 4);
    uint32_t* olp = reinterpret_cast<uint32_t*>(ol + row * CDIM + tid * 4);
    ohp[0] = h0; ohp[1] = h1;
    olp[0] = l0p; olp[1] = l1p;
}

// ---------------------------------------------------------------------------
// Host orchestration
// ---------------------------------------------------------------------------
extern "C" void kernel_launch(void* const* d_in, const int* in_sizes, int n_in,
                              void* d_out, int out_size)
{
    const int*   idx     = (const int*)  d_in[0];
    const float* tok_emb = (const float*)d_in[1];
    const float* pos_emb = (const float*)d_in[2];
    const float* ln1_w   = (const float*)d_in[3];
    const float* ln1_b   = (const float*)d_in[4];
    const float* wq      = (const float*)d_in[5];
    const float* bq      = (const float*)d_in[6];
    const float* wk      = (const float*)d_in[7];
    const float* bk      = (const float*)d_in[8];
    const float* wv      = (const float*)d_in[9];
    const float* bv      = (const float*)d_in[10];
    const float* ln2_w   = (const float*)d_in[11];
    const float* ln2_b   = (const float*)d_in[12];
    const float* w1      = (const float*)d_in[13];
    const float* b1      = (const float*)d_in[14];
    const float* w2      = (const float*)d_in[15];
    const float* b2      = (const float*)d_in[16];
    const float* lnf_w   = (const float*)d_in[17];
    const float* lnf_b   = (const float*)d_in[18];
    const float* head_w  = (const float*)d_in[19];
    float* out = (float*)d_out;

    cudaFuncSetAttribute(hmma_gemm_h2<0, 0, 0>, cudaFuncAttributeMaxDynamicSharedMemorySize, GEMM64_SMEM);
    cudaFuncSetAttribute(hmma_gemm_h2<0, 1, 1>, cudaFuncAttributeMaxDynamicSharedMemorySize, GEMM64_SMEM);
    cudaFuncSetAttribute(hmma_gemm_h2<1, 1, 0>, cudaFuncAttributeMaxDynamicSharedMemorySize, GEMM64_SMEM);
    cudaFuncSetAttribute(hmma_gemm_h1, cudaFuncAttributeMaxDynamicSharedMemorySize, GEMM1_SMEM);
    cudaFuncSetAttribute(flash_attn, cudaFuncAttributeMaxDynamicSharedMemorySize, FA_SMEM);

    float* x;
    cudaGetSymbolAddress((void**)&x, g_x);
    __half *ah, *al, *qkvh, *qkvl, *fh, *fl;
    cudaGetSymbolAddress((void**)&ah, g_ah);
    cudaGetSymbolAddress((void**)&al, g_al);
    cudaGetSymbolAddress((void**)&qkvh, g_qkvh);
    cudaGetSymbolAddress((void**)&qkvl, g_qkvl);
    cudaGetSymbolAddress((void**)&fh, g_fh);
    cudaGetSymbolAddress((void**)&fl, g_fl);
    __half *wqkv16, *w116, *w216, *hw16;
    float* bqkv;
    cudaGetSymbolAddress((void**)&wqkv16, g_wqkv16);
    cudaGetSymbolAddress((void**)&bqkv,   g_bqkv);
    cudaGetSymbolAddress((void**)&w116,  g_w116);
    cudaGetSymbolAddress((void**)&w216,  g_w216);
    cudaGetSymbolAddress((void**)&hw16,  g_hw16);

    // Launch index 3 = layer-0 QKV GEMM (ncu -s 5 capture target).
    transpose_qkv16_kernel<<<dim3(CDIM / 32, CDIM / 32, 3 * NLAYER), 256>>>(
        wq, wk, wv, wqkv16);
    embed_pack_kernel<<<EMBED_BLOCKS + PACK_BLOCKS, 256>>>(
        idx, tok_emb, pos_emb, x, bq, bk, bv, bqkv);
    layernorm_split16_kernel<<<BT, 256>>>(x, ln1_w, ln1_b, ah, al);
    hmma_gemm_h2<0, 1, 1><<<dim3(C3 / 128, BT / 128), 256, GEMM64_SMEM>>>(
        ah, al, wqkv16, bqkv, nullptr, nullptr, qkvh, qkvl, BT, C3, CDIM);
    transpose_f16_kernel<<<dim3(FDIM / 32, CDIM / 32, NLAYER), 256>>>(
        w1, w116, CDIM, FDIM, (size_t)CDIM * FDIM, (size_t)CDIM * FDIM);
    transpose_f16_kernel<<<dim3(CDIM / 32, FDIM / 32, NLAYER), 256>>>(
        w2, w216, FDIM, CDIM, (size_t)CDIM * FDIM, (size_t)CDIM * FDIM);
    transpose_f16_kernel<<<dim3(VDIM / 32, CDIM / 32, 1), 256>>>(
        head_w, hw16, CDIM, VDIM, 0, 0);

    const size_t CC = (size_t)CDIM * CDIM;
    for (int l = 0; l < NLAYER; l++) {
        const size_t oc  = (size_t)l * CDIM;
        const size_t o3  = (size_t)l * 3 * CC;
        const size_t of  = (size_t)l * FDIM;
        const size_t ocf = (size_t)l * CDIM * FDIM;

        if (l > 0) {
            layernorm_split16_kernel<<<BT, 256>>>(x, ln1_w + oc, ln1_b + oc, ah, al);
            hmma_gemm_h2<0, 1, 1><<<dim3(C3 / 128, BT / 128), 256, GEMM64_SMEM>>>(
                ah, al, wqkv16 + o3, bqkv + (size_t)l * C3, nullptr, nullptr,
                qkvh, qkvl, BT, C3, CDIM);
        }

        flash_attn<<<dim3(TLEN / 128, 2 * NH), 256, FA_SMEM>>>(qkvh, qkvl, x);

        layernorm_split16_kernel<<<BT, 256>>>(x, ln2_w + oc, ln2_b + oc, ah, al);
        hmma_gemm_h2<1, 1, 0><<<dim3(FDIM / 128, BT / 128), 256, GEMM64_SMEM>>>(
            ah, al, w116 + ocf, b1 + of, nullptr, nullptr, fh, fl, BT, FDIM, CDIM);
        hmma_gemm_h2<0, 0, 0><<<dim3(CDIM / 128, BT / 128), 256, GEMM64_SMEM>>>(
            fh, fl, w216 + ocf, b2 + oc, x, x, nullptr, nullptr, BT, CDIM, FDIM);
    }

    layernorm_split16_kernel<<<BT, 256>>>(x, lnf_w, lnf_b, ah, al);
    hmma_gemm_h1<<<dim3(VDIM / 128, BT / 128), 256, GEMM1_SMEM>>>(
        ah, hw16, out, BT, VDIM, CDIM);
}

// round 14
// speedup vs baseline: 1.5457x; 1.5457x over previous
#include <cuda_runtime.h>
#include <cuda_bf16.h>
#include <cuda_fp16.h>
#include <math.h>
#include <stdint.h>

// ---------------------------------------------------------------------------
// GPT forward: B=2, T=1024, C=1024, H=16, hd=64, F=4096, V=32000, L=8
// Layer GEMMs + attention: fp16 2-term. Head: 1-term fp16. BK=64.
// R14: revert to R12 interleaved mainloop (R13 hoist blew register budget);
// keep only the safe QLO dead-store skip in the QKV epilogue.
// ---------------------------------------------------------------------------

#define BT 2048
#define CDIM 1024
#define FDIM 4096
#define VDIM 32000
#define NH 16
#define HD 64
#define TLEN 1024
#define NLAYER 8
#define C3 (3 * 1024)

typedef __nv_bfloat16 bf16;

// ------------------------- scratch ------------------------------------------
__device__ __align__(128) float g_x[BT * CDIM];
__device__ __align__(128) __half g_ah[BT * CDIM], g_al[BT * CDIM];
__device__ __align__(128) __half g_qkvh[BT * C3], g_qkvl[BT * C3];
__device__ __align__(128) __half g_fh[BT * FDIM], g_fl[BT * FDIM];
__device__ __align__(128) __half g_wqkv16[NLAYER * C3 * CDIM];
__device__ __align__(128) float g_bqkv[NLAYER * C3];
__device__ __align__(128) __half g_w116[NLAYER * CDIM * FDIM];
__device__ __align__(128) __half g_w216[NLAYER * FDIM * CDIM];
__device__ __align__(128) __half g_hw16[(size_t)VDIM * CDIM];

// ------------------------- PTX helpers --------------------------------------
__device__ __forceinline__ uint32_t smem_u32(const void* p) {
    uint32_t a;
    asm("{ .reg .u64 t; cvta.to.shared.u64 t, %1; cvt.u32.u64 %0, t; }"
        : "=r"(a) : "l"(p));
    return a;
}
__device__ __forceinline__ void cp16(uint32_t dst, const void* src) {
    asm volatile("cp.async.cg.shared.global [%0], [%1], 16;" :: "r"(dst), "l"(src));
}
__device__ __forceinline__ void cp_commit() {
    asm volatile("cp.async.commit_group;" ::: "memory");
}
__device__ __forceinline__ void cp_wait0() {
    asm volatile("cp.async.wait_group 0;" ::: "memory");
}
__device__ __forceinline__ void ldsm4(uint32_t (&r)[4], uint32_t a) {
    asm volatile("ldmatrix.sync.aligned.m8n8.x4.shared.b16 {%0,%1,%2,%3}, [%4];"
        : "=r"(r[0]), "=r"(r[1]), "=r"(r[2]), "=r"(r[3]) : "r"(a));
}
__device__ __forceinline__ void ldsm4t(uint32_t (&r)[4], uint32_t a) {
    asm volatile("ldmatrix.sync.aligned.m8n8.x4.trans.shared.b16 {%0,%1,%2,%3}, [%4];"
        : "=r"(r[0]), "=r"(r[1]), "=r"(r[2]), "=r"(r[3]) : "r"(a));
}
__device__ __forceinline__ void mma16816h(float (&c)[4], const uint32_t (&a)[4],
                                          uint32_t b0, uint32_t b1) {
    asm volatile("mma.sync.aligned.m16n8k16.row.col.f32.f16.f16.f32 "
        "{%0,%1,%2,%3}, {%4,%5,%6,%7}, {%8,%9}, {%0,%1,%2,%3};"
        : "+f"(c[0]), "+f"(c[1]), "+f"(c[2]), "+f"(c[3])
        : "r"(a[0]), "r"(a[1]), "r"(a[2]), "r"(a[3]), "r"(b0), "r"(b1));
}
__device__ __forceinline__ void split2h(float a, float b, uint32_t& hp, uint32_t& lp) {
    __half ha = __float2half_rn(a), hb = __float2half_rn(b);
    __half la = __float2half_rn(a - __half2float(ha));
    __half lb = __float2half_rn(b - __half2float(hb));
    hp = (uint32_t)__half_as_ushort(ha) | ((uint32_t)__half_as_ushort(hb) << 16);
    lp = (uint32_t)__half_as_ushort(la) | ((uint32_t)__half_as_ushort(lb) << 16);
}

#define TSTR64 144
#define TILE64 (128 * TSTR64)          // 18432
#define STAGE64 (3 * TILE64)           // 55296
#define GEMM64_SMEM (2 * STAGE64)      // 110592
#define STAGE1_B (2 * TILE64)          // 36864
#define GEMM1_SMEM (2 * STAGE1_B)      // 73728

// ---------------------------------------------------------------------------
// fp16 2-term 128x128 GEMM, BK=64: C = (Ah+Al)@Bh^T.  (R12 mainloop)
// QLO: when OSPLIT, store lo-plane only for col < 1024 (QKV: K/V lo unused).
// ---------------------------------------------------------------------------
template<int GELU, int OSPLIT, int QLO>
__global__ __launch_bounds__(256, 2) void hmma_gemm_h2(
    const __half* __restrict__ Ah, const __half* __restrict__ Al,
    const __half* __restrict__ Bh,
    const float* __restrict__ bias, const float* __restrict__ resid,
    float* __restrict__ C, __half* __restrict__ Oh, __half* __restrict__ Ol,
    int M, int N, int K)
{
    extern __shared__ char sm[];
    const uint32_t sb = smem_u32(sm);
    const int tid = threadIdx.x;
    const int wid = tid >> 5;
    const int lid = tid & 31;
    const int bn = blockIdx.x * 128;
    const int bm = blockIdx.y * 128;
    const int wm = (wid & 3) * 32;
    const int wn = (wid >> 2) * 64;

    float acc[2][8][4];
    #pragma unroll
    for (int i = 0; i < 2; i++)
        #pragma unroll
        for (int j = 0; j < 8; j++)
            #pragma unroll
            for (int t = 0; t < 4; t++) acc[i][j][t] = 0.f;

    const uint32_t aoff = (uint32_t)((lid & 15) * TSTR64 + (lid >> 4) * 16);
    const uint32_t boff = (uint32_t)(((lid & 7) + (lid >> 4) * 8) * TSTR64
                                     + ((lid >> 3) & 1) * 16);
    const int nch = K >> 6;

    auto load_stage = [&](int ch, int s) {
        const int k0 = ch << 6;
        const uint32_t sbase = sb + s * STAGE64;
        #pragma unroll
        for (int u = 0; u < 4; u++) {
            int f = tid + u * 256;
            int r = f >> 3, c = f & 7;
            uint32_t so = (uint32_t)(r * TSTR64 + c * 16);
            size_t ga = (size_t)(bm + r) * K + k0 + c * 8;
            size_t gb = (size_t)(bn + r) * K + k0 + c * 8;
            cp16(sbase + 0 * TILE64 + so, Ah + ga);
            cp16(sbase + 1 * TILE64 + so, Al + ga);
            cp16(sbase + 2 * TILE64 + so, Bh + gb);
        }
    };

    load_stage(0, 0);
    cp_commit();

    for (int ch = 0; ch < nch; ch++) {
        const int s = ch & 1;
        cp_wait0();
        __syncthreads();
        if (ch + 1 < nch) {
            load_stage(ch + 1, s ^ 1);
            cp_commit();
        }

        const uint32_t stg = sb + s * STAGE64;
        #pragma unroll
        for (int ks = 0; ks < 4; ks++) {
            uint32_t ah_[2][4], al_[2][4];
            #pragma unroll
            for (int mb = 0; mb < 2; mb++) {
                uint32_t abase = stg + (uint32_t)((wm + mb * 16) * TSTR64)
                                 + aoff + ks * 32;
                ldsm4(ah_[mb], abase);
                ldsm4(al_[mb], abase + TILE64);
            }
            #pragma unroll
            for (int nb2 = 0; nb2 < 4; nb2++) {
                uint32_t bh_[4];
                uint32_t bbase = stg + 2 * TILE64
                                 + (uint32_t)((wn + nb2 * 16) * TSTR64)
                                 + boff + ks * 32;
                ldsm4(bh_, bbase);
                #pragma unroll
                for (int mb = 0; mb < 2; mb++) {
                    mma16816h(acc[mb][nb2 * 2 + 0], ah_[mb], bh_[0], bh_[1]);
                    mma16816h(acc[mb][nb2 * 2 + 1], ah_[mb], bh_[2], bh_[3]);
                    mma16816h(acc[mb][nb2 * 2 + 0], al_[mb], bh_[0], bh_[1]);
                    mma16816h(acc[mb][nb2 * 2 + 1], al_[mb], bh_[2], bh_[3]);
                }
            }
        }
    }

    const int er = bm + wm + (lid >> 2);
    const int ec = bn + wn + (lid & 3) * 2;
    #pragma unroll
    for (int mb = 0; mb < 2; mb++) {
        #pragma unroll
        for (int half = 0; half < 2; half++) {
            const int row = er + mb * 16 + half * 8;
            #pragma unroll
            for (int nb = 0; nb < 8; nb++) {
                const int col = ec + nb * 8;
                float v0 = acc[mb][nb][half * 2 + 0];
                float v1 = acc[mb][nb][half * 2 + 1];
                if (bias) { v0 += bias[col]; v1 += bias[col + 1]; }
                if (GELU) {
                    v0 = 0.5f * v0 * (1.0f + erff(v0 * 0.70710678118654752f));
                    v1 = 0.5f * v1 * (1.0f + erff(v1 * 0.70710678118654752f));
                }
                if (OSPLIT) {
                    uint32_t hp, lp;
                    split2h(v0, v1, hp, lp);
                    *reinterpret_cast<uint32_t*>(Oh + (size_t)row * N + col) = hp;
                    if (!QLO || col < 1024)
                        *reinterpret_cast<uint32_t*>(Ol + (size_t)row * N + col) = lp;
                } else {
                    if (resid) {
                        const float* rr = resid + (size_t)row * N;
                        v0 += rr[col]; v1 += rr[col + 1];
                    }
                    *reinterpret_cast<float2*>(C + (size_t)row * N + col) =
                        make_float2(v0, v1);
                }
            }
        }
    }
}

// ---------------------------------------------------------------------------
// fp16 1-term 128x128 GEMM, BK=64 (head): C = Ah@Bh^T (fp32 out). (R12 loop)
// ---------------------------------------------------------------------------
__global__ __launch_bounds__(256, 2) void hmma_gemm_h1(
    const __half* __restrict__ Ah, const __half* __restrict__ Bh,
    float* __restrict__ C, int M, int N, int K)
{
    extern __shared__ char sm[];
    const uint32_t sb = smem_u32(sm);
    const int tid = threadIdx.x;
    const int wid = tid >> 5;
    const int lid = tid & 31;
    const int bn = blockIdx.x * 128;
    const int bm = blockIdx.y * 128;
    const int wm = (wid & 3) * 32;
    const int wn = (wid >> 2) * 64;

    float acc[2][8][4];
    #pragma unroll
    for (int i = 0; i < 2; i++)
        #pragma unroll
        for (int j = 0; j < 8; j++)
            #pragma unroll
            for (int t = 0; t < 4; t++) acc[i][j][t] = 0.f;

    const uint32_t aoff = (uint32_t)((lid & 15) * TSTR64 + (lid >> 4) * 16);
    const uint32_t boff = (uint32_t)(((lid & 7) + (lid >> 4) * 8) * TSTR64
                                     + ((lid >> 3) & 1) * 16);
    const int nch = K >> 6;

    auto load_stage = [&](int ch, int s) {
        const int k0 = ch << 6;
        const uint32_t sbase = sb + s * STAGE1_B;
        #pragma unroll
        for (int u = 0; u < 4; u++) {
            int f = tid + u * 256;
            int r = f >> 3, c = f & 7;
            uint32_t so = (uint32_t)(r * TSTR64 + c * 16);
            size_t ga = (size_t)(bm + r) * K + k0 + c * 8;
            size_t gb = (size_t)(bn + r) * K + k0 + c * 8;
            cp16(sbase + 0 * TILE64 + so, Ah + ga);
            cp16(sbase + 1 * TILE64 + so, Bh + gb);
        }
    };

    load_stage(0, 0);
    cp_commit();

    for (int ch = 0; ch < nch; ch++) {
        const int s = ch & 1;
        cp_wait0();
        __syncthreads();
        if (ch + 1 < nch) {
            load_stage(ch + 1, s ^ 1);
            cp_commit();
        }

        const uint32_t stg = sb + s * STAGE1_B;
        #pragma unroll
        for (int ks = 0; ks < 4; ks++) {
            uint32_t ah_[2][4];
            #pragma unroll
            for (int mb = 0; mb < 2; mb++) {
                uint32_t abase = stg + (uint32_t)((wm + mb * 16) * TSTR64)
                                 + aoff + ks * 32;
                ldsm4(ah_[mb], abase);
            }
            #pragma unroll
            for (int nb2 = 0; nb2 < 4; nb2++) {
                uint32_t bh_[4];
                uint32_t bbase = stg + TILE64
                                 + (uint32_t)((wn + nb2 * 16) * TSTR64)
                                 + boff + ks * 32;
                ldsm4(bh_, bbase);
                #pragma unroll
                for (int mb = 0; mb < 2; mb++) {
                    mma16816h(acc[mb][nb2 * 2 + 0], ah_[mb], bh_[0], bh_[1]);
                    mma16816h(acc[mb][nb2 * 2 + 1], ah_[mb], bh_[2], bh_[3]);
                }
            }
        }
    }

    const int er = bm + wm + (lid >> 2);
    const int ec = bn + wn + (lid & 3) * 2;
    #pragma unroll
    for (int mb = 0; mb < 2; mb++) {
        #pragma unroll
        for (int half = 0; half < 2; half++) {
            const int row = er + mb * 16 + half * 8;
            #pragma unroll
            for (int nb = 0; nb < 8; nb++) {
                const int col = ec + nb * 8;
                *reinterpret_cast<float2*>(C + (size_t)row * N + col) =
                    make_float2(acc[mb][nb][half * 2 + 0],
                                acc[mb][nb][half * 2 + 1]);
            }
        }
    }
}

// ---------------------------------------------------------------------------
// Flash attention, fp16: Q 2-term, K/V single fp16. (unchanged from R12)
// ---------------------------------------------------------------------------
#define XSTR 3072
#define FSTR 144
#define FKTILE (64 * FSTR)
#define FA_STAGE (2 * FKTILE)
#define FA_SMEM  (2 * FA_STAGE)

__global__ __launch_bounds__(256) void flash_attn(
    const __half* __restrict__ qkvh, const __half* __restrict__ qkvl,
    float* __restrict__ x)
{
    extern __shared__ char sm[];
    const uint32_t sb = smem_u32(sm);
    const int tid = threadIdx.x;
    const int wid = tid >> 5;
    const int lid = tid & 31;
    const int qt = blockIdx.x;
    const int bh = blockIdx.y;
    const int b = bh >> 4, h = bh & 15;
    const size_t qrow0 = (size_t)b * TLEN + qt * 128;
    const size_t krow0 = (size_t)b * TLEN;
    const int hoff = h * HD;
    const int wm = wid * 16;

    auto load_kv = [&](int ssn, int s) {
        const size_t srow0 = krow0 + (size_t)ssn * 64;
        const uint32_t stb = sb + s * FA_STAGE;
        #pragma unroll
        for (int u = 0; u < 4; u++) {
            int f = tid + u * 256;
            int buf = f >> 9, r = (f >> 3) & 63, c = f & 7;
            int coloff = 1024 + (buf << 10) + hoff + c * 8;
            cp16(stb + buf * FKTILE + r * FSTR + c * 16,
                 qkvh + (srow0 + r) * XSTR + coloff);
        }
    };

    #pragma unroll
    for (int u = 0; u < 8; u++) {
        int f = tid + u * 256;
        int buf = f >> 10, r = (f >> 3) & 127, c = f & 7;
        const __half* src = buf ? qkvl : qkvh;
        cp16(sb + buf * 18432 + r * FSTR + c * 16,
             src + (qrow0 + r) * XSTR + hoff + c * 8);
    }
    cp_commit();
    cp_wait0();
    __syncthreads();

    uint32_t qfh[4][4], qfl[4][4];
    {
        uint32_t qaddr = sb + (uint32_t)((wm + (lid & 15)) * FSTR + (lid >> 4) * 16);
        #pragma unroll
        for (int ks = 0; ks < 4; ks++) {
            ldsm4(qfh[ks], qaddr + ks * 32);
            ldsm4(qfl[ks], qaddr + 18432 + ks * 32);
        }
    }
    __syncthreads();

    load_kv(0, 0);
    cp_commit();

    float oacc[8][4];
    #pragma unroll
    for (int i = 0; i < 8; i++)
        #pragma unroll
        for (int j = 0; j < 4; j++) oacc[i][j] = 0.f;
    float m0 = -1e30f, m1 = -1e30f, l0 = 0.f, l1 = 0.f;

    const int r_lo = lid >> 2;
    const int cb = (lid & 3) * 2;
    const uint32_t kboff = (uint32_t)(((lid & 7) + ((lid >> 4) << 3)) * FSTR
                                      + (((lid >> 3) & 1) << 4));
    const uint32_t vboff = (uint32_t)((((lid >> 3) & 1) * 8 + (lid & 7)) * FSTR
                                      + ((lid >> 4) << 4));
    const int ssmax = 2 * qt + 1;

    for (int ss = 0; ss <= ssmax; ss++) {
        const int s = ss & 1;
        cp_wait0();
        __syncthreads();
        if (ss < ssmax) {
            load_kv(ss + 1, s ^ 1);
            cp_commit();
        }

        const bool active = (ss * 64) <= (qt * 128 + wm + 15);
        if (active) {
            const uint32_t stg = sb + s * FA_STAGE;
            float sacc[8][4];
            #pragma unroll
            for (int i = 0; i < 8; i++)
                #pragma unroll
                for (int j = 0; j < 4; j++) sacc[i][j] = 0.f;
            #pragma unroll
            for (int nb2 = 0; nb2 < 4; nb2++) {
                #pragma unroll
                for (int ks = 0; ks < 4; ks++) {
                    uint32_t bhreg[4];
                    uint32_t a_ = stg + kboff + (uint32_t)(nb2 * 16 * FSTR) + ks * 32;
                    ldsm4(bhreg, a_);
                    mma16816h(sacc[nb2 * 2 + 0], qfh[ks], bhreg[0], bhreg[1]);
                    mma16816h(sacc[nb2 * 2 + 1], qfh[ks], bhreg[2], bhreg[3]);
                    mma16816h(sacc[nb2 * 2 + 0], qfl[ks], bhreg[0], bhreg[1]);
                    mma16816h(sacc[nb2 * 2 + 1], qfl[ks], bhreg[2], bhreg[3]);
                }
            }
            const int t0g = qt * 128 + wm + r_lo;
            #pragma unroll
            for (int nb = 0; nb < 8; nb++) {
                #pragma unroll
                for (int j = 0; j < 4; j++) {
                    float v = sacc[nb][j] * 0.125f;
                    int s_g = ss * 64 + nb * 8 + cb + (j & 1);
                    int t_g = t0g + (j >> 1) * 8;
                    sacc[nb][j] = (s_g > t_g) ? -1e30f : v;
                }
            }
            float mx0 = -1e30f, mx1 = -1e30f;
            #pragma unroll
            for (int nb = 0; nb < 8; nb++) {
                mx0 = fmaxf(mx0, fmaxf(sacc[nb][0], sacc[nb][1]));
                mx1 = fmaxf(mx1, fmaxf(sacc[nb][2], sacc[nb][3]));
            }
            mx0 = fmaxf(mx0, __shfl_xor_sync(0xffffffffu, mx0, 1));
            mx0 = fmaxf(mx0, __shfl_xor_sync(0xffffffffu, mx0, 2));
            mx1 = fmaxf(mx1, __shfl_xor_sync(0xffffffffu, mx1, 1));
            mx1 = fmaxf(mx1, __shfl_xor_sync(0xffffffffu, mx1, 2));
            float nm0 = fmaxf(m0, mx0), nm1 = fmaxf(m1, mx1);
            float f0 = __expf(m0 - nm0), f1 = __expf(m1 - nm1);
            m0 = nm0; m1 = nm1;
            float rs0 = 0.f, rs1 = 0.f;
            #pragma unroll
            for (int nb = 0; nb < 8; nb++) {
                float p0 = __expf(sacc[nb][0] - nm0);
                float p1 = __expf(sacc[nb][1] - nm0);
                float p2 = __expf(sacc[nb][2] - nm1);
                float p3 = __expf(sacc[nb][3] - nm1);
                sacc[nb][0] = p0; sacc[nb][1] = p1;
                sacc[nb][2] = p2; sacc[nb][3] = p3;
                rs0 += p0 + p1; rs1 += p2 + p3;
            }
            rs0 += __shfl_xor_sync(0xffffffffu, rs0, 1);
            rs0 += __shfl_xor_sync(0xffffffffu, rs0, 2);
            rs1 += __shfl_xor_sync(0xffffffffu, rs1, 1);
            rs1 += __shfl_xor_sync(0xffffffffu, rs1, 2);
            l0 = l0 * f0 + rs0;
            l1 = l1 * f1 + rs1;
            #pragma unroll
            for (int i = 0; i < 8; i++) {
                oacc[i][0] *= f0; oacc[i][1] *= f0;
                oacc[i][2] *= f1; oacc[i][3] *= f1;
            }
            #pragma unroll
            for (int kk = 0; kk < 4; kk++) {
                uint32_t ph[4], pl[4];
                split2h(sacc[2 * kk][0], sacc[2 * kk][1], ph[0], pl[0]);
                split2h(sacc[2 * kk][2], sacc[2 * kk][3], ph[1], pl[1]);
                split2h(sacc[2 * kk + 1][0], sacc[2 * kk + 1][1], ph[2], pl[2]);
                split2h(sacc[2 * kk + 1][2], sacc[2 * kk + 1][3], ph[3], pl[3]);
                #pragma unroll
                for (int db2 = 0; db2 < 4; db2++) {
                    uint32_t vhreg[4];
                    uint32_t va = stg + FKTILE
                                  + (uint32_t)(kk * 16 * FSTR) + vboff
                                  + (uint32_t)(db2 * 32);
                    ldsm4t(vhreg, va);
                    mma16816h(oacc[db2 * 2 + 0], ph, vhreg[0], vhreg[1]);
                    mma16816h(oacc[db2 * 2 + 1], ph, vhreg[2], vhreg[3]);
                    mma16816h(oacc[db2 * 2 + 0], pl, vhreg[0], vhreg[1]);
                    mma16816h(oacc[db2 * 2 + 1], pl, vhreg[2], vhreg[3]);
                }
            }
        }
        __syncthreads();
    }

    const float inv0 = 1.0f / l0;
    const float inv1 = 1.0f / l1;
    const size_t tr0 = qrow0 + wm + r_lo;
    const size_t tr1 = tr0 + 8;
    #pragma unroll
    for (int db = 0; db < 8; db++) {
        const int col = hoff + db * 8 + cb;
        x[tr0 * CDIM + col]     += oacc[db][0] * inv0;
        x[tr0 * CDIM + col + 1] += oacc[db][1] * inv0;
        x[tr1 * CDIM + col]     += oacc[db][2] * inv1;
        x[tr1 * CDIM + col + 1] += oacc[db][3] * inv1;
    }
}

// ---------------------------------------------------------------------------
// Weight prep
// ---------------------------------------------------------------------------
__global__ __launch_bounds__(256) void transpose_f16_kernel(
    const float* __restrict__ W, __half* __restrict__ T, int K, int N,
    size_t src_lstride, size_t dst_lstride)
{
    __shared__ float ts[32][33];
    W += src_lstride * blockIdx.z;
    T += dst_lstride * blockIdx.z;
    const int n0 = blockIdx.x * 32, k0 = blockIdx.y * 32;
    const int tx = threadIdx.x & 31, ty = threadIdx.x >> 5;

    #pragma unroll
    for (int rr = 0; rr < 32; rr += 8)
        ts[ty + rr][tx] = W[(size_t)(k0 + ty + rr) * N + n0 + tx];
    __syncthreads();
    #pragma unroll
    for (int rr = 0; rr < 32; rr += 8)
        T[(size_t)(n0 + ty + rr) * K + k0 + tx] = __float2half_rn(ts[tx][ty + rr]);
}

__global__ __launch_bounds__(256) void transpose_qkv16_kernel(
    const float* __restrict__ wq, const float* __restrict__ wk,
    const float* __restrict__ wv, __half* __restrict__ T)
{
    __shared__ float ts[32][33];
    const int z = blockIdx.z;
    const int l = z / 3, sec = z % 3;
    const size_t CC = (size_t)CDIM * CDIM;
    const float* W = ((sec == 0) ? wq : (sec == 1) ? wk : wv) + (size_t)l * CC;
    __half* t = T + (size_t)l * 3 * CC + (size_t)sec * CC;
    const int n0 = blockIdx.x * 32, k0 = blockIdx.y * 32;
    const int tx = threadIdx.x & 31, ty = threadIdx.x >> 5;

    #pragma unroll
    for (int rr = 0; rr < 32; rr += 8)
        ts[ty + rr][tx] = W[(size_t)(k0 + ty + rr) * CDIM + n0 + tx];
    __syncthreads();
    #pragma unroll
    for (int rr = 0; rr < 32; rr += 8)
        t[(size_t)(n0 + ty + rr) * CDIM + k0 + tx] = __float2half_rn(ts[tx][ty + rr]);
}

// ---------------------------------------------------------------------------
// Embedding + QKV bias packing (fused)
// ---------------------------------------------------------------------------
#define EMBED_BLOCKS (BT * CDIM / 256)
#define PACK_BLOCKS  ((NLAYER * C3 + 255) / 256)

__global__ __launch_bounds__(256) void embed_pack_kernel(
    const int* __restrict__ idx, const float* __restrict__ tok,
    const float* __restrict__ pos, float* __restrict__ x,
    const float* __restrict__ bq, const float* __restrict__ bk,
    const float* __restrict__ bv, float* __restrict__ bqkv)
{
    if (blockIdx.x < EMBED_BLOCKS) {
        int i = blockIdx.x * 256 + threadIdx.x;
        int n = i >> 10;
        int c = i & (CDIM - 1);
        int t = n & (TLEN - 1);
        x[i] = tok[(size_t)idx[n] * CDIM + c] + pos[(size_t)t * CDIM + c];
    } else {
        int i = (blockIdx.x - EMBED_BLOCKS) * 256 + threadIdx.x;
        if (i < NLAYER * C3) {
            int l = i / C3, rem = i % C3, sec = rem >> 10, c = rem & 1023;
            const float* src = (sec == 0) ? bq : (sec == 1) ? bk : bv;
            bqkv[i] = src[l * CDIM + c];
        }
    }
}

// ---------------------------------------------------------------------------
// LayerNorm -> fp16 split pair
// ---------------------------------------------------------------------------
__global__ __launch_bounds__(256) void layernorm_split16_kernel(
    const float* __restrict__ x, const float* __restrict__ w,
    const float* __restrict__ b, __half* __restrict__ oh, __half* __restrict__ ol)
{
    __shared__ float2 sh[8];
    const size_t row = blockIdx.x;
    const int tid = threadIdx.x;
    const float* xr = x + row * CDIM;

    float4 v = *reinterpret_cast<const float4*>(&xr[tid * 4]);
    float s  = v.x + v.y + v.z + v.w;
    float ss = v.x * v.x + v.y * v.y + v.z * v.z + v.w * v.w;
    #pragma unroll
    for (int o = 16; o > 0; o >>= 1) {
        s  += __shfl_xor_sync(0xffffffffu, s,  o);
        ss += __shfl_xor_sync(0xffffffffu, ss, o);
    }
    if ((tid & 31) == 0) sh[tid >> 5] = make_float2(s, ss);
    __syncthreads();
    float ts = 0.f, tss = 0.f;
    #pragma unroll
    for (int i = 0; i < 8; i++) { ts += sh[i].x; tss += sh[i].y; }
    const float mu  = ts * (1.0f / CDIM);
    const float var = tss * (1.0f / CDIM) - mu * mu;
    const float rstd = rsqrtf(var + 1e-5f);

    float4 wv = *reinterpret_cast<const float4*>(&w[tid * 4]);
    float4 bv = *reinterpret_cast<const float4*>(&b[tid * 4]);
    float o0 = (v.x - mu) * rstd * wv.x + bv.x;
    float o1 = (v.y - mu) * rstd * wv.y + bv.y;
    float o2 = (v.z - mu) * rstd * wv.z + bv.z;
    float o3 = (v.w - mu) * rstd * wv.w + bv.w;
    uint32_t h0, l0p, h1, l1p;
    split2h(o0, o1, h0, l0p);
    split2h(o2, o3, h1, l1p);
    uint32_t* ohp = reinterpret_cast<uint32_t*>(oh + row * CDIM + tid * 4);
    uint32_t* olp = reinterpret_cast<uint32_t*>(ol + row * CDIM + tid * 4);
    ohp[0] = h0; ohp[1] = h1;
    olp[0] = l0p; olp[1] = l1p;
}

// ---------------------------------------------------------------------------
// Host orchestration
// ---------------------------------------------------------------------------
extern "C" void kernel_launch(void* const* d_in, const int* in_sizes, int n_in,
                              void* d_out, int out_size)
{
    const int*   idx     = (const int*)  d_in[0];
    const float* tok_emb = (const float*)d_in[1];
    const float* pos_emb = (const float*)d_in[2];
    const float* ln1_w   = (const float*)d_in[3];
    const float* ln1_b   = (const float*)d_in[4];
    const float* wq      = (const float*)d_in[5];
    const float* bq      = (const float*)d_in[6];
    const float* wk      = (const float*)d_in[7];
    const float* bk      = (const float*)d_in[8];
    const float* wv      = (const float*)d_in[9];
    const float* bv      = (const float*)d_in[10];
    const float* ln2_w   = (const float*)d_in[11];
    const float* ln2_b   = (const float*)d_in[12];
    const float* w1      = (const float*)d_in[13];
    const float* b1      = (const float*)d_in[14];
    const float* w2      = (const float*)d_in[15];
    const float* b2      = (const float*)d_in[16];
    const float* lnf_w   = (const float*)d_in[17];
    const float* lnf_b   = (const float*)d_in[18];
    const float* head_w  = (const float*)d_in[19];
    float* out = (float*)d_out;

    cudaFuncSetAttribute(hmma_gemm_h2<0, 0, 0>, cudaFuncAttributeMaxDynamicSharedMemorySize, GEMM64_SMEM);
    cudaFuncSetAttribute(hmma_gemm_h2<0, 1, 1>, cudaFuncAttributeMaxDynamicSharedMemorySize, GEMM64_SMEM);
    cudaFuncSetAttribute(hmma_gemm_h2<1, 1, 0>, cudaFuncAttributeMaxDynamicSharedMemorySize, GEMM64_SMEM);
    cudaFuncSetAttribute(hmma_gemm_h1, cudaFuncAttributeMaxDynamicSharedMemorySize, GEMM1_SMEM);
    cudaFuncSetAttribute(flash_attn, cudaFuncAttributeMaxDynamicSharedMemorySize, FA_SMEM);

    float* x;
    cudaGetSymbolAddress((void**)&x, g_x);
    __half *ah, *al, *qkvh, *qkvl, *fh, *fl;
    cudaGetSymbolAddress((void**)&ah, g_ah);
    cudaGetSymbolAddress((void**)&al, g_al);
    cudaGetSymbolAddress((void**)&qkvh, g_qkvh);
    cudaGetSymbolAddress((void**)&qkvl, g_qkvl);
    cudaGetSymbolAddress((void**)&fh, g_fh);
    cudaGetSymbolAddress((void**)&fl, g_fl);
    __half *wqkv16, *w116, *w216, *hw16;
    float* bqkv;
    cudaGetSymbolAddress((void**)&wqkv16, g_wqkv16);
    cudaGetSymbolAddress((void**)&bqkv,   g_bqkv);
    cudaGetSymbolAddress((void**)&w116,  g_w116);
    cudaGetSymbolAddress((void**)&w216,  g_w216);
    cudaGetSymbolAddress((void**)&hw16,  g_hw16);

    transpose_qkv16_kernel<<<dim3(CDIM / 32, CDIM / 32, 3 * NLAYER), 256>>>(
        wq, wk, wv, wqkv16);
    embed_pack_kernel<<<EMBED_BLOCKS + PACK_BLOCKS, 256>>>(
        idx, tok_emb, pos_emb, x, bq, bk, bv, bqkv);
    layernorm_split16_kernel<<<BT, 256>>>(x, ln1_w, ln1_b, ah, al);
    hmma_gemm_h2<0, 1, 1><<<dim3(C3 / 128, BT / 128), 256, GEMM64_SMEM>>>(
        ah, al, wqkv16, bqkv, nullptr, nullptr, qkvh, qkvl, BT, C3, CDIM);
    transpose_f16_kernel<<<dim3(FDIM / 32, CDIM / 32, NLAYER), 256>>>(
        w1, w116, CDIM, FDIM, (size_t)CDIM * FDIM, (size_t)CDIM * FDIM);
    transpose_f16_kernel<<<dim3(CDIM / 32, FDIM / 32, NLAYER), 256>>>(
        w2, w216, FDIM, CDIM, (size_t)CDIM * FDIM, (size_t)CDIM * FDIM);
    transpose_f16_kernel<<<dim3(VDIM / 32, CDIM / 32, 1), 256>>>(
        head_w, hw16, CDIM, VDIM, 0, 0);

    const size_t CC = (size_t)CDIM * CDIM;
    for (int l = 0; l < NLAYER; l++) {
        const size_t oc  = (size_t)l * CDIM;
        const size_t o3  = (size_t)l * 3 * CC;
        const size_t of  = (size_t)l * FDIM;
        const size_t ocf = (size_t)l * CDIM * FDIM;

        if (l > 0) {
            layernorm_split16_kernel<<<BT, 256>>>(x, ln1_w + oc, ln1_b + oc, ah, al);
            hmma_gemm_h2<0, 1, 1><<<dim3(C3 / 128, BT / 128), 256, GEMM64_SMEM>>>(
                ah, al, wqkv16 + o3, bqkv + (size_t)l * C3, nullptr, nullptr,
                qkvh, qkvl, BT, C3, CDIM);
        }

        flash_attn<<<dim3(TLEN / 128, 2 * NH), 256, FA_SMEM>>>(qkvh, qkvl, x);

        layernorm_split16_kernel<<<BT, 256>>>(x, ln2_w + oc, ln2_b + oc, ah, al);
        hmma_gemm_h2<1, 1, 0><<<dim3(FDIM / 128, BT / 128), 256, GEMM64_SMEM>>>(
            ah, al, w116 + ocf, b1 + of, nullptr, nullptr, fh, fl, BT, FDIM, CDIM);
        hmma_gemm_h2<0, 0, 0><<<dim3(CDIM / 128, BT / 128), 256, GEMM64_SMEM>>>(
            fh, fl, w216 + ocf, b2 + oc, x, x, nullptr, nullptr, BT, CDIM, FDIM);
    }

    layernorm_split16_kernel<<<BT, 256>>>(x, lnf_w, lnf_b, ah, al);
    hmma_gemm_h1<<<dim3(VDIM / 128, BT / 128), 256, GEMM1_SMEM>>>(
        ah, hw16, out, BT, VDIM, CDIM);
}

// round 15
// speedup vs baseline: 1.7139x; 1.1088x over previous
#include <cuda_runtime.h>
#include <cuda_bf16.h>
#include <cuda_fp16.h>
#include <math.h>
#include <stdint.h>

// ---------------------------------------------------------------------------
// GPT forward: B=2, T=1024, C=1024, H=16, hd=64, F=4096, V=32000, L=8
// QKV/FFN2: fp16 2-term.  FFN1 + head: 1-term fp16.  FA: Q 2-term, K/V 1-term.
// BK=64 interleaved mainloop (R12/R14 schedule). QLO dead-store skip.
// ---------------------------------------------------------------------------

#define BT 2048
#define CDIM 1024
#define FDIM 4096
#define VDIM 32000
#define NH 16
#define HD 64
#define TLEN 1024
#define NLAYER 8
#define C3 (3 * 1024)

typedef __nv_bfloat16 bf16;

// ------------------------- scratch ------------------------------------------
__device__ __align__(128) float g_x[BT * CDIM];
__device__ __align__(128) __half g_ah[BT * CDIM], g_al[BT * CDIM];
__device__ __align__(128) __half g_qkvh[BT * C3], g_qkvl[BT * C3];
__device__ __align__(128) __half g_fh[BT * FDIM], g_fl[BT * FDIM];
__device__ __align__(128) __half g_wqkv16[NLAYER * C3 * CDIM];
__device__ __align__(128) float g_bqkv[NLAYER * C3];
__device__ __align__(128) __half g_w116[NLAYER * CDIM * FDIM];
__device__ __align__(128) __half g_w216[NLAYER * FDIM * CDIM];
__device__ __align__(128) __half g_hw16[(size_t)VDIM * CDIM];

// ------------------------- PTX helpers --------------------------------------
__device__ __forceinline__ uint32_t smem_u32(const void* p) {
    uint32_t a;
    asm("{ .reg .u64 t; cvta.to.shared.u64 t, %1; cvt.u32.u64 %0, t; }"
        : "=r"(a) : "l"(p));
    return a;
}
__device__ __forceinline__ void cp16(uint32_t dst, const void* src) {
    asm volatile("cp.async.cg.shared.global [%0], [%1], 16;" :: "r"(dst), "l"(src));
}
__device__ __forceinline__ void cp_commit() {
    asm volatile("cp.async.commit_group;" ::: "memory");
}
__device__ __forceinline__ void cp_wait0() {
    asm volatile("cp.async.wait_group 0;" ::: "memory");
}
__device__ __forceinline__ void ldsm4(uint32_t (&r)[4], uint32_t a) {
    asm volatile("ldmatrix.sync.aligned.m8n8.x4.shared.b16 {%0,%1,%2,%3}, [%4];"
        : "=r"(r[0]), "=r"(r[1]), "=r"(r[2]), "=r"(r[3]) : "r"(a));
}
__device__ __forceinline__ void ldsm4t(uint32_t (&r)[4], uint32_t a) {
    asm volatile("ldmatrix.sync.aligned.m8n8.x4.trans.shared.b16 {%0,%1,%2,%3}, [%4];"
        : "=r"(r[0]), "=r"(r[1]), "=r"(r[2]), "=r"(r[3]) : "r"(a));
}
__device__ __forceinline__ void mma16816h(float (&c)[4], const uint32_t (&a)[4],
                                          uint32_t b0, uint32_t b1) {
    asm volatile("mma.sync.aligned.m16n8k16.row.col.f32.f16.f16.f32 "
        "{%0,%1,%2,%3}, {%4,%5,%6,%7}, {%8,%9}, {%0,%1,%2,%3};"
        : "+f"(c[0]), "+f"(c[1]), "+f"(c[2]), "+f"(c[3])
        : "r"(a[0]), "r"(a[1]), "r"(a[2]), "r"(a[3]), "r"(b0), "r"(b1));
}
__device__ __forceinline__ void split2h(float a, float b, uint32_t& hp, uint32_t& lp) {
    __half ha = __float2half_rn(a), hb = __float2half_rn(b);
    __half la = __float2half_rn(a - __half2float(ha));
    __half lb = __float2half_rn(b - __half2float(hb));
    hp = (uint32_t)__half_as_ushort(ha) | ((uint32_t)__half_as_ushort(hb) << 16);
    lp = (uint32_t)__half_as_ushort(la) | ((uint32_t)__half_as_ushort(lb) << 16);
}

#define TSTR64 144
#define TILE64 (128 * TSTR64)          // 18432
#define STAGE64 (3 * TILE64)           // 55296
#define GEMM64_SMEM (2 * STAGE64)      // 110592
#define STAGE1_B (2 * TILE64)          // 36864
#define GEMM1_SMEM (2 * STAGE1_B)      // 73728

// ---------------------------------------------------------------------------
// fp16 2-term 128x128 GEMM, BK=64: C = (Ah+Al)@Bh^T.  (R12 mainloop)
// QLO: when OSPLIT, store lo-plane only for col < 1024 (QKV: K/V lo unused).
// ---------------------------------------------------------------------------
template<int GELU, int OSPLIT, int QLO>
__global__ __launch_bounds__(256, 2) void hmma_gemm_h2(
    const __half* __restrict__ Ah, const __half* __restrict__ Al,
    const __half* __restrict__ Bh,
    const float* __restrict__ bias, const float* __restrict__ resid,
    float* __restrict__ C, __half* __restrict__ Oh, __half* __restrict__ Ol,
    int M, int N, int K)
{
    extern __shared__ char sm[];
    const uint32_t sb = smem_u32(sm);
    const int tid = threadIdx.x;
    const int wid = tid >> 5;
    const int lid = tid & 31;
    const int bn = blockIdx.x * 128;
    const int bm = blockIdx.y * 128;
    const int wm = (wid & 3) * 32;
    const int wn = (wid >> 2) * 64;

    float acc[2][8][4];
    #pragma unroll
    for (int i = 0; i < 2; i++)
        #pragma unroll
        for (int j = 0; j < 8; j++)
            #pragma unroll
            for (int t = 0; t < 4; t++) acc[i][j][t] = 0.f;

    const uint32_t aoff = (uint32_t)((lid & 15) * TSTR64 + (lid >> 4) * 16);
    const uint32_t boff = (uint32_t)(((lid & 7) + (lid >> 4) * 8) * TSTR64
                                     + ((lid >> 3) & 1) * 16);
    const int nch = K >> 6;

    auto load_stage = [&](int ch, int s) {
        const int k0 = ch << 6;
        const uint32_t sbase = sb + s * STAGE64;
        #pragma unroll
        for (int u = 0; u < 4; u++) {
            int f = tid + u * 256;
            int r = f >> 3, c = f & 7;
            uint32_t so = (uint32_t)(r * TSTR64 + c * 16);
            size_t ga = (size_t)(bm + r) * K + k0 + c * 8;
            size_t gb = (size_t)(bn + r) * K + k0 + c * 8;
            cp16(sbase + 0 * TILE64 + so, Ah + ga);
            cp16(sbase + 1 * TILE64 + so, Al + ga);
            cp16(sbase + 2 * TILE64 + so, Bh + gb);
        }
    };

    load_stage(0, 0);
    cp_commit();

    for (int ch = 0; ch < nch; ch++) {
        const int s = ch & 1;
        cp_wait0();
        __syncthreads();
        if (ch + 1 < nch) {
            load_stage(ch + 1, s ^ 1);
            cp_commit();
        }

        const uint32_t stg = sb + s * STAGE64;
        #pragma unroll
        for (int ks = 0; ks < 4; ks++) {
            uint32_t ah_[2][4], al_[2][4];
            #pragma unroll
            for (int mb = 0; mb < 2; mb++) {
                uint32_t abase = stg + (uint32_t)((wm + mb * 16) * TSTR64)
                                 + aoff + ks * 32;
                ldsm4(ah_[mb], abase);
                ldsm4(al_[mb], abase + TILE64);
            }
            #pragma unroll
            for (int nb2 = 0; nb2 < 4; nb2++) {
                uint32_t bh_[4];
                uint32_t bbase = stg + 2 * TILE64
                                 + (uint32_t)((wn + nb2 * 16) * TSTR64)
                                 + boff + ks * 32;
                ldsm4(bh_, bbase);
                #pragma unroll
                for (int mb = 0; mb < 2; mb++) {
                    mma16816h(acc[mb][nb2 * 2 + 0], ah_[mb], bh_[0], bh_[1]);
                    mma16816h(acc[mb][nb2 * 2 + 1], ah_[mb], bh_[2], bh_[3]);
                    mma16816h(acc[mb][nb2 * 2 + 0], al_[mb], bh_[0], bh_[1]);
                    mma16816h(acc[mb][nb2 * 2 + 1], al_[mb], bh_[2], bh_[3]);
                }
            }
        }
    }

    const int er = bm + wm + (lid >> 2);
    const int ec = bn + wn + (lid & 3) * 2;
    #pragma unroll
    for (int mb = 0; mb < 2; mb++) {
        #pragma unroll
        for (int half = 0; half < 2; half++) {
            const int row = er + mb * 16 + half * 8;
            #pragma unroll
            for (int nb = 0; nb < 8; nb++) {
                const int col = ec + nb * 8;
                float v0 = acc[mb][nb][half * 2 + 0];
                float v1 = acc[mb][nb][half * 2 + 1];
                if (bias) { v0 += bias[col]; v1 += bias[col + 1]; }
                if (GELU) {
                    v0 = 0.5f * v0 * (1.0f + erff(v0 * 0.70710678118654752f));
                    v1 = 0.5f * v1 * (1.0f + erff(v1 * 0.70710678118654752f));
                }
                if (OSPLIT) {
                    uint32_t hp, lp;
                    split2h(v0, v1, hp, lp);
                    *reinterpret_cast<uint32_t*>(Oh + (size_t)row * N + col) = hp;
                    if (!QLO || col < 1024)
                        *reinterpret_cast<uint32_t*>(Ol + (size_t)row * N + col) = lp;
                } else {
                    if (resid) {
                        const float* rr = resid + (size_t)row * N;
                        v0 += rr[col]; v1 += rr[col + 1];
                    }
                    *reinterpret_cast<float2*>(C + (size_t)row * N + col) =
                        make_float2(v0, v1);
                }
            }
        }
    }
}

// ---------------------------------------------------------------------------
// fp16 1-term 128x128 GEMM, BK=64: C = Ah@Bh^T.
// Epilogues: OSPLIT=1 -> (+bias)(+GELU) split fp16 pair; OSPLIT=0 -> fp32 C.
// Used for FFN1 (GELU+split) and head (raw fp32).
// ---------------------------------------------------------------------------
template<int GELU, int OSPLIT>
__global__ __launch_bounds__(256, 2) void hmma_gemm_h1(
    const __half* __restrict__ Ah, const __half* __restrict__ Bh,
    const float* __restrict__ bias, float* __restrict__ C,
    __half* __restrict__ Oh, __half* __restrict__ Ol,
    int M, int N, int K)
{
    extern __shared__ char sm[];
    const uint32_t sb = smem_u32(sm);
    const int tid = threadIdx.x;
    const int wid = tid >> 5;
    const int lid = tid & 31;
    const int bn = blockIdx.x * 128;
    const int bm = blockIdx.y * 128;
    const int wm = (wid & 3) * 32;
    const int wn = (wid >> 2) * 64;

    float acc[2][8][4];
    #pragma unroll
    for (int i = 0; i < 2; i++)
        #pragma unroll
        for (int j = 0; j < 8; j++)
            #pragma unroll
            for (int t = 0; t < 4; t++) acc[i][j][t] = 0.f;

    const uint32_t aoff = (uint32_t)((lid & 15) * TSTR64 + (lid >> 4) * 16);
    const uint32_t boff = (uint32_t)(((lid & 7) + (lid >> 4) * 8) * TSTR64
                                     + ((lid >> 3) & 1) * 16);
    const int nch = K >> 6;

    auto load_stage = [&](int ch, int s) {
        const int k0 = ch << 6;
        const uint32_t sbase = sb + s * STAGE1_B;
        #pragma unroll
        for (int u = 0; u < 4; u++) {
            int f = tid + u * 256;
            int r = f >> 3, c = f & 7;
            uint32_t so = (uint32_t)(r * TSTR64 + c * 16);
            size_t ga = (size_t)(bm + r) * K + k0 + c * 8;
            size_t gb = (size_t)(bn + r) * K + k0 + c * 8;
            cp16(sbase + 0 * TILE64 + so, Ah + ga);
            cp16(sbase + 1 * TILE64 + so, Bh + gb);
        }
    };

    load_stage(0, 0);
    cp_commit();

    for (int ch = 0; ch < nch; ch++) {
        const int s = ch & 1;
        cp_wait0();
        __syncthreads();
        if (ch + 1 < nch) {
            load_stage(ch + 1, s ^ 1);
            cp_commit();
        }

        const uint32_t stg = sb + s * STAGE1_B;
        #pragma unroll
        for (int ks = 0; ks < 4; ks++) {
            uint32_t ah_[2][4];
            #pragma unroll
            for (int mb = 0; mb < 2; mb++) {
                uint32_t abase = stg + (uint32_t)((wm + mb * 16) * TSTR64)
                                 + aoff + ks * 32;
                ldsm4(ah_[mb], abase);
            }
            #pragma unroll
            for (int nb2 = 0; nb2 < 4; nb2++) {
                uint32_t bh_[4];
                uint32_t bbase = stg + TILE64
                                 + (uint32_t)((wn + nb2 * 16) * TSTR64)
                                 + boff + ks * 32;
                ldsm4(bh_, bbase);
                #pragma unroll
                for (int mb = 0; mb < 2; mb++) {
                    mma16816h(acc[mb][nb2 * 2 + 0], ah_[mb], bh_[0], bh_[1]);
                    mma16816h(acc[mb][nb2 * 2 + 1], ah_[mb], bh_[2], bh_[3]);
                }
            }
        }
    }

    const int er = bm + wm + (lid >> 2);
    const int ec = bn + wn + (lid & 3) * 2;
    #pragma unroll
    for (int mb = 0; mb < 2; mb++) {
        #pragma unroll
        for (int half = 0; half < 2; half++) {
            const int row = er + mb * 16 + half * 8;
            #pragma unroll
            for (int nb = 0; nb < 8; nb++) {
                const int col = ec + nb * 8;
                float v0 = acc[mb][nb][half * 2 + 0];
                float v1 = acc[mb][nb][half * 2 + 1];
                if (bias) { v0 += bias[col]; v1 += bias[col + 1]; }
                if (GELU) {
                    v0 = 0.5f * v0 * (1.0f + erff(v0 * 0.70710678118654752f));
                    v1 = 0.5f * v1 * (1.0f + erff(v1 * 0.70710678118654752f));
                }
                if (OSPLIT) {
                    uint32_t hp, lp;
                    split2h(v0, v1, hp, lp);
                    *reinterpret_cast<uint32_t*>(Oh + (size_t)row * N + col) = hp;
                    *reinterpret_cast<uint32_t*>(Ol + (size_t)row * N + col) = lp;
                } else {
                    *reinterpret_cast<float2*>(C + (size_t)row * N + col) =
                        make_float2(v0, v1);
                }
            }
        }
    }
}

// ---------------------------------------------------------------------------
// Flash attention, fp16: Q 2-term, K/V single fp16. (unchanged from R14)
// ---------------------------------------------------------------------------
#define XSTR 3072
#define FSTR 144
#define FKTILE (64 * FSTR)
#define FA_STAGE (2 * FKTILE)
#define FA_SMEM  (2 * FA_STAGE)

__global__ __launch_bounds__(256) void flash_attn(
    const __half* __restrict__ qkvh, const __half* __restrict__ qkvl,
    float* __restrict__ x)
{
    extern __shared__ char sm[];
    const uint32_t sb = smem_u32(sm);
    const int tid = threadIdx.x;
    const int wid = tid >> 5;
    const int lid = tid & 31;
    const int qt = blockIdx.x;
    const int bh = blockIdx.y;
    const int b = bh >> 4, h = bh & 15;
    const size_t qrow0 = (size_t)b * TLEN + qt * 128;
    const size_t krow0 = (size_t)b * TLEN;
    const int hoff = h * HD;
    const int wm = wid * 16;

    auto load_kv = [&](int ssn, int s) {
        const size_t srow0 = krow0 + (size_t)ssn * 64;
        const uint32_t stb = sb + s * FA_STAGE;
        #pragma unroll
        for (int u = 0; u < 4; u++) {
            int f = tid + u * 256;
            int buf = f >> 9, r = (f >> 3) & 63, c = f & 7;
            int coloff = 1024 + (buf << 10) + hoff + c * 8;
            cp16(stb + buf * FKTILE + r * FSTR + c * 16,
                 qkvh + (srow0 + r) * XSTR + coloff);
        }
    };

    #pragma unroll
    for (int u = 0; u < 8; u++) {
        int f = tid + u * 256;
        int buf = f >> 10, r = (f >> 3) & 127, c = f & 7;
        const __half* src = buf ? qkvl : qkvh;
        cp16(sb + buf * 18432 + r * FSTR + c * 16,
             src + (qrow0 + r) * XSTR + hoff + c * 8);
    }
    cp_commit();
    cp_wait0();
    __syncthreads();

    uint32_t qfh[4][4], qfl[4][4];
    {
        uint32_t qaddr = sb + (uint32_t)((wm + (lid & 15)) * FSTR + (lid >> 4) * 16);
        #pragma unroll
        for (int ks = 0; ks < 4; ks++) {
            ldsm4(qfh[ks], qaddr + ks * 32);
            ldsm4(qfl[ks], qaddr + 18432 + ks * 32);
        }
    }
    __syncthreads();

    load_kv(0, 0);
    cp_commit();

    float oacc[8][4];
    #pragma unroll
    for (int i = 0; i < 8; i++)
        #pragma unroll
        for (int j = 0; j < 4; j++) oacc[i][j] = 0.f;
    float m0 = -1e30f, m1 = -1e30f, l0 = 0.f, l1 = 0.f;

    const int r_lo = lid >> 2;
    const int cb = (lid & 3) * 2;
    const uint32_t kboff = (uint32_t)(((lid & 7) + ((lid >> 4) << 3)) * FSTR
                                      + (((lid >> 3) & 1) << 4));
    const uint32_t vboff = (uint32_t)((((lid >> 3) & 1) * 8 + (lid & 7)) * FSTR
                                      + ((lid >> 4) << 4));
    const int ssmax = 2 * qt + 1;

    for (int ss = 0; ss <= ssmax; ss++) {
        const int s = ss & 1;
        cp_wait0();
        __syncthreads();
        if (ss < ssmax) {
            load_kv(ss + 1, s ^ 1);
            cp_commit();
        }

        const bool active = (ss * 64) <= (qt * 128 + wm + 15);
        if (active) {
            const uint32_t stg = sb + s * FA_STAGE;
            float sacc[8][4];
            #pragma unroll
            for (int i = 0; i < 8; i++)
                #pragma unroll
                for (int j = 0; j < 4; j++) sacc[i][j] = 0.f;
            #pragma unroll
            for (int nb2 = 0; nb2 < 4; nb2++) {
                #pragma unroll
                for (int ks = 0; ks < 4; ks++) {
                    uint32_t bhreg[4];
                    uint32_t a_ = stg + kboff + (uint32_t)(nb2 * 16 * FSTR) + ks * 32;
                    ldsm4(bhreg, a_);
                    mma16816h(sacc[nb2 * 2 + 0], qfh[ks], bhreg[0], bhreg[1]);
                    mma16816h(sacc[nb2 * 2 + 1], qfh[ks], bhreg[2], bhreg[3]);
                    mma16816h(sacc[nb2 * 2 + 0], qfl[ks], bhreg[0], bhreg[1]);
                    mma16816h(sacc[nb2 * 2 + 1], qfl[ks], bhreg[2], bhreg[3]);
                }
            }
            const int t0g = qt * 128 + wm + r_lo;
            #pragma unroll
            for (int nb = 0; nb < 8; nb++) {
                #pragma unroll
                for (int j = 0; j < 4; j++) {
                    float v = sacc[nb][j] * 0.125f;
                    int s_g = ss * 64 + nb * 8 + cb + (j & 1);
                    int t_g = t0g + (j >> 1) * 8;
                    sacc[nb][j] = (s_g > t_g) ? -1e30f : v;
                }
            }
            float mx0 = -1e30f, mx1 = -1e30f;
            #pragma unroll
            for (int nb = 0; nb < 8; nb++) {
                mx0 = fmaxf(mx0, fmaxf(sacc[nb][0], sacc[nb][1]));
                mx1 = fmaxf(mx1, fmaxf(sacc[nb][2], sacc[nb][3]));
            }
            mx0 = fmaxf(mx0, __shfl_xor_sync(0xffffffffu, mx0, 1));
            mx0 = fmaxf(mx0, __shfl_xor_sync(0xffffffffu, mx0, 2));
            mx1 = fmaxf(mx1, __shfl_xor_sync(0xffffffffu, mx1, 1));
            mx1 = fmaxf(mx1, __shfl_xor_sync(0xffffffffu, mx1, 2));
            float nm0 = fmaxf(m0, mx0), nm1 = fmaxf(m1, mx1);
            float f0 = __expf(m0 - nm0), f1 = __expf(m1 - nm1);
            m0 = nm0; m1 = nm1;
            float rs0 = 0.f, rs1 = 0.f;
            #pragma unroll
            for (int nb = 0; nb < 8; nb++) {
                float p0 = __expf(sacc[nb][0] - nm0);
                float p1 = __expf(sacc[nb][1] - nm0);
                float p2 = __expf(sacc[nb][2] - nm1);
                float p3 = __expf(sacc[nb][3] - nm1);
                sacc[nb][0] = p0; sacc[nb][1] = p1;
                sacc[nb][2] = p2; sacc[nb][3] = p3;
                rs0 += p0 + p1; rs1 += p2 + p3;
            }
            rs0 += __shfl_xor_sync(0xffffffffu, rs0, 1);
            rs0 += __shfl_xor_sync(0xffffffffu, rs0, 2);
            rs1 += __shfl_xor_sync(0xffffffffu, rs1, 1);
            rs1 += __shfl_xor_sync(0xffffffffu, rs1, 2);
            l0 = l0 * f0 + rs0;
            l1 = l1 * f1 + rs1;
            #pragma unroll
            for (int i = 0; i < 8; i++) {
                oacc[i][0] *= f0; oacc[i][1] *= f0;
                oacc[i][2] *= f1; oacc[i][3] *= f1;
            }
            #pragma unroll
            for (int kk = 0; kk < 4; kk++) {
                uint32_t ph[4], pl[4];
                split2h(sacc[2 * kk][0], sacc[2 * kk][1], ph[0], pl[0]);
                split2h(sacc[2 * kk][2], sacc[2 * kk][3], ph[1], pl[1]);
                split2h(sacc[2 * kk + 1][0], sacc[2 * kk + 1][1], ph[2], pl[2]);
                split2h(sacc[2 * kk + 1][2], sacc[2 * kk + 1][3], ph[3], pl[3]);
                #pragma unroll
                for (int db2 = 0; db2 < 4; db2++) {
                    uint32_t vhreg[4];
                    uint32_t va = stg + FKTILE
                                  + (uint32_t)(kk * 16 * FSTR) + vboff
                                  + (uint32_t)(db2 * 32);
                    ldsm4t(vhreg, va);
                    mma16816h(oacc[db2 * 2 + 0], ph, vhreg[0], vhreg[1]);
                    mma16816h(oacc[db2 * 2 + 1], ph, vhreg[2], vhreg[3]);
                    mma16816h(oacc[db2 * 2 + 0], pl, vhreg[0], vhreg[1]);
                    mma16816h(oacc[db2 * 2 + 1], pl, vhreg[2], vhreg[3]);
                }
            }
        }
        __syncthreads();
    }

    const float inv0 = 1.0f / l0;
    const float inv1 = 1.0f / l1;
    const size_t tr0 = qrow0 + wm + r_lo;
    const size_t tr1 = tr0 + 8;
    #pragma unroll
    for (int db = 0; db < 8; db++) {
        const int col = hoff + db * 8 + cb;
        x[tr0 * CDIM + col]     += oacc[db][0] * inv0;
        x[tr0 * CDIM + col + 1] += oacc[db][1] * inv0;
        x[tr1 * CDIM + col]     += oacc[db][2] * inv1;
        x[tr1 * CDIM + col + 1] += oacc[db][3] * inv1;
    }
}

// ---------------------------------------------------------------------------
// Weight prep
// ---------------------------------------------------------------------------
__global__ __launch_bounds__(256) void transpose_f16_kernel(
    const float* __restrict__ W, __half* __restrict__ T, int K, int N,
    size_t src_lstride, size_t dst_lstride)
{
    __shared__ float ts[32][33];
    W += src_lstride * blockIdx.z;
    T += dst_lstride * blockIdx.z;
    const int n0 = blockIdx.x * 32, k0 = blockIdx.y * 32;
    const int tx = threadIdx.x & 31, ty = threadIdx.x >> 5;

    #pragma unroll
    for (int rr = 0; rr < 32; rr += 8)
        ts[ty + rr][tx] = W[(size_t)(k0 + ty + rr) * N + n0 + tx];
    __syncthreads();
    #pragma unroll
    for (int rr = 0; rr < 32; rr += 8)
        T[(size_t)(n0 + ty + rr) * K + k0 + tx] = __float2half_rn(ts[tx][ty + rr]);
}

__global__ __launch_bounds__(256) void transpose_qkv16_kernel(
    const float* __restrict__ wq, const float* __restrict__ wk,
    const float* __restrict__ wv, __half* __restrict__ T)
{
    __shared__ float ts[32][33];
    const int z = blockIdx.z;
    const int l = z / 3, sec = z % 3;
    const size_t CC = (size_t)CDIM * CDIM;
    const float* W = ((sec == 0) ? wq : (sec == 1) ? wk : wv) + (size_t)l * CC;
    __half* t = T + (size_t)l * 3 * CC + (size_t)sec * CC;
    const int n0 = blockIdx.x * 32, k0 = blockIdx.y * 32;
    const int tx = threadIdx.x & 31, ty = threadIdx.x >> 5;

    #pragma unroll
    for (int rr = 0; rr < 32; rr += 8)
        ts[ty + rr][tx] = W[(size_t)(k0 + ty + rr) * CDIM + n0 + tx];
    __syncthreads();
    #pragma unroll
    for (int rr = 0; rr < 32; rr += 8)
        t[(size_t)(n0 + ty + rr) * CDIM + k0 + tx] = __float2half_rn(ts[tx][ty + rr]);
}

// ---------------------------------------------------------------------------
// Embedding + QKV bias packing (fused)
// ---------------------------------------------------------------------------
#define EMBED_BLOCKS (BT * CDIM / 256)
#define PACK_BLOCKS  ((NLAYER * C3 + 255) / 256)

__global__ __launch_bounds__(256) void embed_pack_kernel(
    const int* __restrict__ idx, const float* __restrict__ tok,
    const float* __restrict__ pos, float* __restrict__ x,
    const float* __restrict__ bq, const float* __restrict__ bk,
    const float* __restrict__ bv, float* __restrict__ bqkv)
{
    if (blockIdx.x < EMBED_BLOCKS) {
        int i = blockIdx.x * 256 + threadIdx.x;
        int n = i >> 10;
        int c = i & (CDIM - 1);
        int t = n & (TLEN - 1);
        x[i] = tok[(size_t)idx[n] * CDIM + c] + pos[(size_t)t * CDIM + c];
    } else {
        int i = (blockIdx.x - EMBED_BLOCKS) * 256 + threadIdx.x;
        if (i < NLAYER * C3) {
            int l = i / C3, rem = i % C3, sec = rem >> 10, c = rem & 1023;
            const float* src = (sec == 0) ? bq : (sec == 1) ? bk : bv;
            bqkv[i] = src[l * CDIM + c];
        }
    }
}

// ---------------------------------------------------------------------------
// LayerNorm -> fp16 split pair
// ---------------------------------------------------------------------------
__global__ __launch_bounds__(256) void layernorm_split16_kernel(
    const float* __restrict__ x, const float* __restrict__ w,
    const float* __restrict__ b, __half* __restrict__ oh, __half* __restrict__ ol)
{
    __shared__ float2 sh[8];
    const size_t row = blockIdx.x;
    const int tid = threadIdx.x;
    const float* xr = x + row * CDIM;

    float4 v = *reinterpret_cast<const float4*>(&xr[tid * 4]);
    float s  = v.x + v.y + v.z + v.w;
    float ss = v.x * v.x + v.y * v.y + v.z * v.z + v.w * v.w;
    #pragma unroll
    for (int o = 16; o > 0; o >>= 1) {
        s  += __shfl_xor_sync(0xffffffffu, s,  o);
        ss += __shfl_xor_sync(0xffffffffu, ss, o);
    }
    if ((tid & 31) == 0) sh[tid >> 5] = make_float2(s, ss);
    __syncthreads();
    float ts = 0.f, tss = 0.f;
    #pragma unroll
    for (int i = 0; i < 8; i++) { ts += sh[i].x; tss += sh[i].y; }
    const float mu  = ts * (1.0f / CDIM);
    const float var = tss * (1.0f / CDIM) - mu * mu;
    const float rstd = rsqrtf(var + 1e-5f);

    float4 wv = *reinterpret_cast<const float4*>(&w[tid * 4]);
    float4 bv = *reinterpret_cast<const float4*>(&b[tid * 4]);
    float o0 = (v.x - mu) * rstd * wv.x + bv.x;
    float o1 = (v.y - mu) * rstd * wv.y + bv.y;
    float o2 = (v.z - mu) * rstd * wv.z + bv.z;
    float o3 = (v.w - mu) * rstd * wv.w + bv.w;
    uint32_t h0, l0p, h1, l1p;
    split2h(o0, o1, h0, l0p);
    split2h(o2, o3, h1, l1p);
    uint32_t* ohp = reinterpret_cast<uint32_t*>(oh + row * CDIM + tid * 4);
    uint32_t* olp = reinterpret_cast<uint32_t*>(ol + row * CDIM + tid * 4);
    ohp[0] = h0; ohp[1] = h1;
    olp[0] = l0p; olp[1] = l1p;
}

// ---------------------------------------------------------------------------
// Host orchestration
// ---------------------------------------------------------------------------
extern "C" void kernel_launch(void* const* d_in, const int* in_sizes, int n_in,
                              void* d_out, int out_size)
{
    const int*   idx     = (const int*)  d_in[0];
    const float* tok_emb = (const float*)d_in[1];
    const float* pos_emb = (const float*)d_in[2];
    const float* ln1_w   = (const float*)d_in[3];
    const float* ln1_b   = (const float*)d_in[4];
    const float* wq      = (const float*)d_in[5];
    const float* bq      = (const float*)d_in[6];
    const float* wk      = (const float*)d_in[7];
    const float* bk      = (const float*)d_in[8];
    const float* wv      = (const float*)d_in[9];
    const float* bv      = (const float*)d_in[10];
    const float* ln2_w   = (const float*)d_in[11];
    const float* ln2_b   = (const float*)d_in[12];
    const float* w1      = (const float*)d_in[13];
    const float* b1      = (const float*)d_in[14];
    const float* w2      = (const float*)d_in[15];
    const float* b2      = (const float*)d_in[16];
    const float* lnf_w   = (const float*)d_in[17];
    const float* lnf_b   = (const float*)d_in[18];
    const float* head_w  = (const float*)d_in[19];
    float* out = (float*)d_out;

    cudaFuncSetAttribute(hmma_gemm_h2<0, 0, 0>, cudaFuncAttributeMaxDynamicSharedMemorySize, GEMM64_SMEM);
    cudaFuncSetAttribute(hmma_gemm_h2<0, 1, 1>, cudaFuncAttributeMaxDynamicSharedMemorySize, GEMM64_SMEM);
    cudaFuncSetAttribute(hmma_gemm_h1<1, 1>, cudaFuncAttributeMaxDynamicSharedMemorySize, GEMM1_SMEM);
    cudaFuncSetAttribute(hmma_gemm_h1<0, 0>, cudaFuncAttributeMaxDynamicSharedMemorySize, GEMM1_SMEM);
    cudaFuncSetAttribute(flash_attn, cudaFuncAttributeMaxDynamicSharedMemorySize, FA_SMEM);

    float* x;
    cudaGetSymbolAddress((void**)&x, g_x);
    __half *ah, *al, *qkvh, *qkvl, *fh, *fl;
    cudaGetSymbolAddress((void**)&ah, g_ah);
    cudaGetSymbolAddress((void**)&al, g_al);
    cudaGetSymbolAddress((void**)&qkvh, g_qkvh);
    cudaGetSymbolAddress((void**)&qkvl, g_qkvl);
    cudaGetSymbolAddress((void**)&fh, g_fh);
    cudaGetSymbolAddress((void**)&fl, g_fl);
    __half *wqkv16, *w116, *w216, *hw16;
    float* bqkv;
    cudaGetSymbolAddress((void**)&wqkv16, g_wqkv16);
    cudaGetSymbolAddress((void**)&bqkv,   g_bqkv);
    cudaGetSymbolAddress((void**)&w116,  g_w116);
    cudaGetSymbolAddress((void**)&w216,  g_w216);
    cudaGetSymbolAddress((void**)&hw16,  g_hw16);

    transpose_qkv16_kernel<<<dim3(CDIM / 32, CDIM / 32, 3 * NLAYER), 256>>>(
        wq, wk, wv, wqkv16);
    embed_pack_kernel<<<EMBED_BLOCKS + PACK_BLOCKS, 256>>>(
        idx, tok_emb, pos_emb, x, bq, bk, bv, bqkv);
    layernorm_split16_kernel<<<BT, 256>>>(x, ln1_w, ln1_b, ah, al);
    hmma_gemm_h2<0, 1, 1><<<dim3(C3 / 128, BT / 128), 256, GEMM64_SMEM>>>(
        ah, al, wqkv16, bqkv, nullptr, nullptr, qkvh, qkvl, BT, C3, CDIM);
    transpose_f16_kernel<<<dim3(FDIM / 32, CDIM / 32, NLAYER), 256>>>(
        w1, w116, CDIM, FDIM, (size_t)CDIM * FDIM, (size_t)CDIM * FDIM);
    transpose_f16_kernel<<<dim3(CDIM / 32, FDIM / 32, NLAYER), 256>>>(
        w2, w216, FDIM, CDIM, (size_t)CDIM * FDIM, (size_t)CDIM * FDIM);
    transpose_f16_kernel<<<dim3(VDIM / 32, CDIM / 32, 1), 256>>>(
        head_w, hw16, CDIM, VDIM, 0, 0);

    const size_t CC = (size_t)CDIM * CDIM;
    for (int l = 0; l < NLAYER; l++) {
        const size_t oc  = (size_t)l * CDIM;
        const size_t o3  = (size_t)l * 3 * CC;
        const size_t of  = (size_t)l * FDIM;
        const size_t ocf = (size_t)l * CDIM * FDIM;

        if (l > 0) {
            layernorm_split16_kernel<<<BT, 256>>>(x, ln1_w + oc, ln1_b + oc, ah, al);
            hmma_gemm_h2<0, 1, 1><<<dim3(C3 / 128, BT / 128), 256, GEMM64_SMEM>>>(
                ah, al, wqkv16 + o3, bqkv + (size_t)l * C3, nullptr, nullptr,
                qkvh, qkvl, BT, C3, CDIM);
        }

        flash_attn<<<dim3(TLEN / 128, 2 * NH), 256, FA_SMEM>>>(qkvh, qkvl, x);

        layernorm_split16_kernel<<<BT, 256>>>(x, ln2_w + oc, ln2_b + oc, ah, al);
        // FFN1: 1-term fp16 (A hi plane only) + bias + GELU -> fp16 split pair
        hmma_gemm_h1<1, 1><<<dim3(FDIM / 128, BT / 128), 256, GEMM1_SMEM>>>(
            ah, w116 + ocf, b1 + of, nullptr, fh, fl, BT, FDIM, CDIM);
        // FFN2: 2-term fp16 + bias + residual -> fp32 x
        hmma_gemm_h2<0, 0, 0><<<dim3(CDIM / 128, BT / 128), 256, GEMM64_SMEM>>>(
            fh, fl, w216 + ocf, b2 + oc, x, x, nullptr, nullptr, BT, CDIM, FDIM);
    }

    // final LN -> fp16 (hi plane used), head GEMM 1-term fp16 -> fp32 logits
    layernorm_split16_kernel<<<BT, 256>>>(x, lnf_w, lnf_b, ah, al);
    hmma_gemm_h1<0, 0><<<dim3(VDIM / 128, BT / 128), 256, GEMM1_SMEM>>>(
        ah, hw16, nullptr, out, nullptr, nullptr, BT, VDIM, CDIM);
}

// round 16
// speedup vs baseline: 1.7608x; 1.0274x over previous
#include <cuda_runtime.h>
#include <cuda_bf16.h>
#include <cuda_fp16.h>
#include <math.h>
#include <stdint.h>

// ---------------------------------------------------------------------------
// GPT forward: B=2, T=1024, C=1024, H=16, hd=64, F=4096, V=32000, L=8
// QKV/FFN2: fp16 2-term. FFN1 + head: 1-term fp16.
// FA: Q 2-term, K/V 1-term, P 1-term (R16). BK=64 interleaved mainloop.
// ---------------------------------------------------------------------------

#define BT 2048
#define CDIM 1024
#define FDIM 4096
#define VDIM 32000
#define NH 16
#define HD 64
#define TLEN 1024
#define NLAYER 8
#define C3 (3 * 1024)

typedef __nv_bfloat16 bf16;

// ------------------------- scratch ------------------------------------------
__device__ __align__(128) float g_x[BT * CDIM];
__device__ __align__(128) __half g_ah[BT * CDIM], g_al[BT * CDIM];
__device__ __align__(128) __half g_qkvh[BT * C3], g_qkvl[BT * C3];
__device__ __align__(128) __half g_fh[BT * FDIM], g_fl[BT * FDIM];
__device__ __align__(128) __half g_wqkv16[NLAYER * C3 * CDIM];
__device__ __align__(128) float g_bqkv[NLAYER * C3];
__device__ __align__(128) __half g_w116[NLAYER * CDIM * FDIM];
__device__ __align__(128) __half g_w216[NLAYER * FDIM * CDIM];
__device__ __align__(128) __half g_hw16[(size_t)VDIM * CDIM];

// ------------------------- PTX helpers --------------------------------------
__device__ __forceinline__ uint32_t smem_u32(const void* p) {
    uint32_t a;
    asm("{ .reg .u64 t; cvta.to.shared.u64 t, %1; cvt.u32.u64 %0, t; }"
        : "=r"(a) : "l"(p));
    return a;
}
__device__ __forceinline__ void cp16(uint32_t dst, const void* src) {
    asm volatile("cp.async.cg.shared.global [%0], [%1], 16;" :: "r"(dst), "l"(src));
}
__device__ __forceinline__ void cp_commit() {
    asm volatile("cp.async.commit_group;" ::: "memory");
}
__device__ __forceinline__ void cp_wait0() {
    asm volatile("cp.async.wait_group 0;" ::: "memory");
}
__device__ __forceinline__ void ldsm4(uint32_t (&r)[4], uint32_t a) {
    asm volatile("ldmatrix.sync.aligned.m8n8.x4.shared.b16 {%0,%1,%2,%3}, [%4];"
        : "=r"(r[0]), "=r"(r[1]), "=r"(r[2]), "=r"(r[3]) : "r"(a));
}
__device__ __forceinline__ void ldsm4t(uint32_t (&r)[4], uint32_t a) {
    asm volatile("ldmatrix.sync.aligned.m8n8.x4.trans.shared.b16 {%0,%1,%2,%3}, [%4];"
        : "=r"(r[0]), "=r"(r[1]), "=r"(r[2]), "=r"(r[3]) : "r"(a));
}
__device__ __forceinline__ void mma16816h(float (&c)[4], const uint32_t (&a)[4],
                                          uint32_t b0, uint32_t b1) {
    asm volatile("mma.sync.aligned.m16n8k16.row.col.f32.f16.f16.f32 "
        "{%0,%1,%2,%3}, {%4,%5,%6,%7}, {%8,%9}, {%0,%1,%2,%3};"
        : "+f"(c[0]), "+f"(c[1]), "+f"(c[2]), "+f"(c[3])
        : "r"(a[0]), "r"(a[1]), "r"(a[2]), "r"(a[3]), "r"(b0), "r"(b1));
}
__device__ __forceinline__ void split2h(float a, float b, uint32_t& hp, uint32_t& lp) {
    __half ha = __float2half_rn(a), hb = __float2half_rn(b);
    __half la = __float2half_rn(a - __half2float(ha));
    __half lb = __float2half_rn(b - __half2float(hb));
    hp = (uint32_t)__half_as_ushort(ha) | ((uint32_t)__half_as_ushort(hb) << 16);
    lp = (uint32_t)__half_as_ushort(la) | ((uint32_t)__half_as_ushort(lb) << 16);
}
__device__ __forceinline__ uint32_t pack2h(float a, float b) {
    __half ha = __float2half_rn(a), hb = __float2half_rn(b);
    return (uint32_t)__half_as_ushort(ha) | ((uint32_t)__half_as_ushort(hb) << 16);
}

#define TSTR64 144
#define TILE64 (128 * TSTR64)          // 18432
#define STAGE64 (3 * TILE64)           // 55296
#define GEMM64_SMEM (2 * STAGE64)      // 110592
#define STAGE1_B (2 * TILE64)          // 36864
#define GEMM1_SMEM (2 * STAGE1_B)      // 73728

// ---------------------------------------------------------------------------
// fp16 2-term 128x128 GEMM, BK=64: C = (Ah+Al)@Bh^T.  (R12/R14 mainloop)
// QLO: when OSPLIT, store lo-plane only for col < 1024 (QKV: K/V lo unused).
// ---------------------------------------------------------------------------
template<int GELU, int OSPLIT, int QLO>
__global__ __launch_bounds__(256, 2) void hmma_gemm_h2(
    const __half* __restrict__ Ah, const __half* __restrict__ Al,
    const __half* __restrict__ Bh,
    const float* __restrict__ bias, const float* __restrict__ resid,
    float* __restrict__ C, __half* __restrict__ Oh, __half* __restrict__ Ol,
    int M, int N, int K)
{
    extern __shared__ char sm[];
    const uint32_t sb = smem_u32(sm);
    const int tid = threadIdx.x;
    const int wid = tid >> 5;
    const int lid = tid & 31;
    const int bn = blockIdx.x * 128;
    const int bm = blockIdx.y * 128;
    const int wm = (wid & 3) * 32;
    const int wn = (wid >> 2) * 64;

    float acc[2][8][4];
    #pragma unroll
    for (int i = 0; i < 2; i++)
        #pragma unroll
        for (int j = 0; j < 8; j++)
            #pragma unroll
            for (int t = 0; t < 4; t++) acc[i][j][t] = 0.f;

    const uint32_t aoff = (uint32_t)((lid & 15) * TSTR64 + (lid >> 4) * 16);
    const uint32_t boff = (uint32_t)(((lid & 7) + (lid >> 4) * 8) * TSTR64
                                     + ((lid >> 3) & 1) * 16);
    const int nch = K >> 6;

    auto load_stage = [&](int ch, int s) {
        const int k0 = ch << 6;
        const uint32_t sbase = sb + s * STAGE64;
        #pragma unroll
        for (int u = 0; u < 4; u++) {
            int f = tid + u * 256;
            int r = f >> 3, c = f & 7;
            uint32_t so = (uint32_t)(r * TSTR64 + c * 16);
            size_t ga = (size_t)(bm + r) * K + k0 + c * 8;
            size_t gb = (size_t)(bn + r) * K + k0 + c * 8;
            cp16(sbase + 0 * TILE64 + so, Ah + ga);
            cp16(sbase + 1 * TILE64 + so, Al + ga);
            cp16(sbase + 2 * TILE64 + so, Bh + gb);
        }
    };

    load_stage(0, 0);
    cp_commit();

    for (int ch = 0; ch < nch; ch++) {
        const int s = ch & 1;
        cp_wait0();
        __syncthreads();
        if (ch + 1 < nch) {
            load_stage(ch + 1, s ^ 1);
            cp_commit();
        }

        const uint32_t stg = sb + s * STAGE64;
        #pragma unroll
        for (int ks = 0; ks < 4; ks++) {
            uint32_t ah_[2][4], al_[2][4];
            #pragma unroll
            for (int mb = 0; mb < 2; mb++) {
                uint32_t abase = stg + (uint32_t)((wm + mb * 16) * TSTR64)
                                 + aoff + ks * 32;
                ldsm4(ah_[mb], abase);
                ldsm4(al_[mb], abase + TILE64);
            }
            #pragma unroll
            for (int nb2 = 0; nb2 < 4; nb2++) {
                uint32_t bh_[4];
                uint32_t bbase = stg + 2 * TILE64
                                 + (uint32_t)((wn + nb2 * 16) * TSTR64)
                                 + boff + ks * 32;
                ldsm4(bh_, bbase);
                #pragma unroll
                for (int mb = 0; mb < 2; mb++) {
                    mma16816h(acc[mb][nb2 * 2 + 0], ah_[mb], bh_[0], bh_[1]);
                    mma16816h(acc[mb][nb2 * 2 + 1], ah_[mb], bh_[2], bh_[3]);
                    mma16816h(acc[mb][nb2 * 2 + 0], al_[mb], bh_[0], bh_[1]);
                    mma16816h(acc[mb][nb2 * 2 + 1], al_[mb], bh_[2], bh_[3]);
                }
            }
        }
    }

    const int er = bm + wm + (lid >> 2);
    const int ec = bn + wn + (lid & 3) * 2;
    #pragma unroll
    for (int mb = 0; mb < 2; mb++) {
        #pragma unroll
        for (int half = 0; half < 2; half++) {
            const int row = er + mb * 16 + half * 8;
            #pragma unroll
            for (int nb = 0; nb < 8; nb++) {
                const int col = ec + nb * 8;
                float v0 = acc[mb][nb][half * 2 + 0];
                float v1 = acc[mb][nb][half * 2 + 1];
                if (bias) { v0 += bias[col]; v1 += bias[col + 1]; }
                if (GELU) {
                    v0 = 0.5f * v0 * (1.0f + erff(v0 * 0.70710678118654752f));
                    v1 = 0.5f * v1 * (1.0f + erff(v1 * 0.70710678118654752f));
                }
                if (OSPLIT) {
                    uint32_t hp, lp;
                    split2h(v0, v1, hp, lp);
                    *reinterpret_cast<uint32_t*>(Oh + (size_t)row * N + col) = hp;
                    if (!QLO || col < 1024)
                        *reinterpret_cast<uint32_t*>(Ol + (size_t)row * N + col) = lp;
                } else {
                    if (resid) {
                        const float* rr = resid + (size_t)row * N;
                        v0 += rr[col]; v1 += rr[col + 1];
                    }
                    *reinterpret_cast<float2*>(C + (size_t)row * N + col) =
                        make_float2(v0, v1);
                }
            }
        }
    }
}

// ---------------------------------------------------------------------------
// fp16 1-term 128x128 GEMM, BK=64: C = Ah@Bh^T.  (FFN1 + head)
// ---------------------------------------------------------------------------
template<int GELU, int OSPLIT>
__global__ __launch_bounds__(256, 2) void hmma_gemm_h1(
    const __half* __restrict__ Ah, const __half* __restrict__ Bh,
    const float* __restrict__ bias, float* __restrict__ C,
    __half* __restrict__ Oh, __half* __restrict__ Ol,
    int M, int N, int K)
{
    extern __shared__ char sm[];
    const uint32_t sb = smem_u32(sm);
    const int tid = threadIdx.x;
    const int wid = tid >> 5;
    const int lid = tid & 31;
    const int bn = blockIdx.x * 128;
    const int bm = blockIdx.y * 128;
    const int wm = (wid & 3) * 32;
    const int wn = (wid >> 2) * 64;

    float acc[2][8][4];
    #pragma unroll
    for (int i = 0; i < 2; i++)
        #pragma unroll
        for (int j = 0; j < 8; j++)
            #pragma unroll
            for (int t = 0; t < 4; t++) acc[i][j][t] = 0.f;

    const uint32_t aoff = (uint32_t)((lid & 15) * TSTR64 + (lid >> 4) * 16);
    const uint32_t boff = (uint32_t)(((lid & 7) + (lid >> 4) * 8) * TSTR64
                                     + ((lid >> 3) & 1) * 16);
    const int nch = K >> 6;

    auto load_stage = [&](int ch, int s) {
        const int k0 = ch << 6;
        const uint32_t sbase = sb + s * STAGE1_B;
        #pragma unroll
        for (int u = 0; u < 4; u++) {
            int f = tid + u * 256;
            int r = f >> 3, c = f & 7;
            uint32_t so = (uint32_t)(r * TSTR64 + c * 16);
            size_t ga = (size_t)(bm + r) * K + k0 + c * 8;
            size_t gb = (size_t)(bn + r) * K + k0 + c * 8;
            cp16(sbase + 0 * TILE64 + so, Ah + ga);
            cp16(sbase + 1 * TILE64 + so, Bh + gb);
        }
    };

    load_stage(0, 0);
    cp_commit();

    for (int ch = 0; ch < nch; ch++) {
        const int s = ch & 1;
        cp_wait0();
        __syncthreads();
        if (ch + 1 < nch) {
            load_stage(ch + 1, s ^ 1);
            cp_commit();
        }

        const uint32_t stg = sb + s * STAGE1_B;
        #pragma unroll
        for (int ks = 0; ks < 4; ks++) {
            uint32_t ah_[2][4];
            #pragma unroll
            for (int mb = 0; mb < 2; mb++) {
                uint32_t abase = stg + (uint32_t)((wm + mb * 16) * TSTR64)
                                 + aoff + ks * 32;
                ldsm4(ah_[mb], abase);
            }
            #pragma unroll
            for (int nb2 = 0; nb2 < 4; nb2++) {
                uint32_t bh_[4];
                uint32_t bbase = stg + TILE64
                                 + (uint32_t)((wn + nb2 * 16) * TSTR64)
                                 + boff + ks * 32;
                ldsm4(bh_, bbase);
                #pragma unroll
                for (int mb = 0; mb < 2; mb++) {
                    mma16816h(acc[mb][nb2 * 2 + 0], ah_[mb], bh_[0], bh_[1]);
                    mma16816h(acc[mb][nb2 * 2 + 1], ah_[mb], bh_[2], bh_[3]);
                }
            }
        }
    }

    const int er = bm + wm + (lid >> 2);
    const int ec = bn + wn + (lid & 3) * 2;
    #pragma unroll
    for (int mb = 0; mb < 2; mb++) {
        #pragma unroll
        for (int half = 0; half < 2; half++) {
            const int row = er + mb * 16 + half * 8;
            #pragma unroll
            for (int nb = 0; nb < 8; nb++) {
                const int col = ec + nb * 8;
                float v0 = acc[mb][nb][half * 2 + 0];
                float v1 = acc[mb][nb][half * 2 + 1];
                if (bias) { v0 += bias[col]; v1 += bias[col + 1]; }
                if (GELU) {
                    v0 = 0.5f * v0 * (1.0f + erff(v0 * 0.70710678118654752f));
                    v1 = 0.5f * v1 * (1.0f + erff(v1 * 0.70710678118654752f));
                }
                if (OSPLIT) {
                    uint32_t hp, lp;
                    split2h(v0, v1, hp, lp);
                    *reinterpret_cast<uint32_t*>(Oh + (size_t)row * N + col) = hp;
                    *reinterpret_cast<uint32_t*>(Ol + (size_t)row * N + col) = lp;
                } else {
                    *reinterpret_cast<float2*>(C + (size_t)row * N + col) =
                        make_float2(v0, v1);
                }
            }
        }
    }
}

// ---------------------------------------------------------------------------
// Flash attention, fp16: Q 2-term, K/V 1-term, P 1-term (R16).
// ---------------------------------------------------------------------------
#define XSTR 3072
#define FSTR 144
#define FKTILE (64 * FSTR)
#define FA_STAGE (2 * FKTILE)
#define FA_SMEM  (2 * FA_STAGE)

__global__ __launch_bounds__(256) void flash_attn(
    const __half* __restrict__ qkvh, const __half* __restrict__ qkvl,
    float* __restrict__ x)
{
    extern __shared__ char sm[];
    const uint32_t sb = smem_u32(sm);
    const int tid = threadIdx.x;
    const int wid = tid >> 5;
    const int lid = tid & 31;
    const int qt = blockIdx.x;
    const int bh = blockIdx.y;
    const int b = bh >> 4, h = bh & 15;
    const size_t qrow0 = (size_t)b * TLEN + qt * 128;
    const size_t krow0 = (size_t)b * TLEN;
    const int hoff = h * HD;
    const int wm = wid * 16;

    auto load_kv = [&](int ssn, int s) {
        const size_t srow0 = krow0 + (size_t)ssn * 64;
        const uint32_t stb = sb + s * FA_STAGE;
        #pragma unroll
        for (int u = 0; u < 4; u++) {
            int f = tid + u * 256;
            int buf = f >> 9, r = (f >> 3) & 63, c = f & 7;
            int coloff = 1024 + (buf << 10) + hoff + c * 8;
            cp16(stb + buf * FKTILE + r * FSTR + c * 16,
                 qkvh + (srow0 + r) * XSTR + coloff);
        }
    };

    #pragma unroll
    for (int u = 0; u < 8; u++) {
        int f = tid + u * 256;
        int buf = f >> 10, r = (f >> 3) & 127, c = f & 7;
        const __half* src = buf ? qkvl : qkvh;
        cp16(sb + buf * 18432 + r * FSTR + c * 16,
             src + (qrow0 + r) * XSTR + hoff + c * 8);
    }
    cp_commit();
    cp_wait0();
    __syncthreads();

    uint32_t qfh[4][4], qfl[4][4];
    {
        uint32_t qaddr = sb + (uint32_t)((wm + (lid & 15)) * FSTR + (lid >> 4) * 16);
        #pragma unroll
        for (int ks = 0; ks < 4; ks++) {
            ldsm4(qfh[ks], qaddr + ks * 32);
            ldsm4(qfl[ks], qaddr + 18432 + ks * 32);
        }
    }
    __syncthreads();

    load_kv(0, 0);
    cp_commit();

    float oacc[8][4];
    #pragma unroll
    for (int i = 0; i < 8; i++)
        #pragma unroll
        for (int j = 0; j < 4; j++) oacc[i][j] = 0.f;
    float m0 = -1e30f, m1 = -1e30f, l0 = 0.f, l1 = 0.f;

    const int r_lo = lid >> 2;
    const int cb = (lid & 3) * 2;
    const uint32_t kboff = (uint32_t)(((lid & 7) + ((lid >> 4) << 3)) * FSTR
                                      + (((lid >> 3) & 1) << 4));
    const uint32_t vboff = (uint32_t)((((lid >> 3) & 1) * 8 + (lid & 7)) * FSTR
                                      + ((lid >> 4) << 4));
    const int ssmax = 2 * qt + 1;

    for (int ss = 0; ss <= ssmax; ss++) {
        const int s = ss & 1;
        cp_wait0();
        __syncthreads();
        if (ss < ssmax) {
            load_kv(ss + 1, s ^ 1);
            cp_commit();
        }

        const bool active = (ss * 64) <= (qt * 128 + wm + 15);
        if (active) {
            const uint32_t stg = sb + s * FA_STAGE;
            float sacc[8][4];
            #pragma unroll
            for (int i = 0; i < 8; i++)
                #pragma unroll
                for (int j = 0; j < 4; j++) sacc[i][j] = 0.f;
            #pragma unroll
            for (int nb2 = 0; nb2 < 4; nb2++) {
                #pragma unroll
                for (int ks = 0; ks < 4; ks++) {
                    uint32_t bhreg[4];
                    uint32_t a_ = stg + kboff + (uint32_t)(nb2 * 16 * FSTR) + ks * 32;
                    ldsm4(bhreg, a_);
                    mma16816h(sacc[nb2 * 2 + 0], qfh[ks], bhreg[0], bhreg[1]);
                    mma16816h(sacc[nb2 * 2 + 1], qfh[ks], bhreg[2], bhreg[3]);
                    mma16816h(sacc[nb2 * 2 + 0], qfl[ks], bhreg[0], bhreg[1]);
                    mma16816h(sacc[nb2 * 2 + 1], qfl[ks], bhreg[2], bhreg[3]);
                }
            }
            const int t0g = qt * 128 + wm + r_lo;
            #pragma unroll
            for (int nb = 0; nb < 8; nb++) {
                #pragma unroll
                for (int j = 0; j < 4; j++) {
                    float v = sacc[nb][j] * 0.125f;
                    int s_g = ss * 64 + nb * 8 + cb + (j & 1);
                    int t_g = t0g + (j >> 1) * 8;
                    sacc[nb][j] = (s_g > t_g) ? -1e30f : v;
                }
            }
            float mx0 = -1e30f, mx1 = -1e30f;
            #pragma unroll
            for (int nb = 0; nb < 8; nb++) {
                mx0 = fmaxf(mx0, fmaxf(sacc[nb][0], sacc[nb][1]));
                mx1 = fmaxf(mx1, fmaxf(sacc[nb][2], sacc[nb][3]));
            }
            mx0 = fmaxf(mx0, __shfl_xor_sync(0xffffffffu, mx0, 1));
            mx0 = fmaxf(mx0, __shfl_xor_sync(0xffffffffu, mx0, 2));
            mx1 = fmaxf(mx1, __shfl_xor_sync(0xffffffffu, mx1, 1));
            mx1 = fmaxf(mx1, __shfl_xor_sync(0xffffffffu, mx1, 2));
            float nm0 = fmaxf(m0, mx0), nm1 = fmaxf(m1, mx1);
            float f0 = __expf(m0 - nm0), f1 = __expf(m1 - nm1);
            m0 = nm0; m1 = nm1;
            float rs0 = 0.f, rs1 = 0.f;
            #pragma unroll
            for (int nb = 0; nb < 8; nb++) {
                float p0 = __expf(sacc[nb][0] - nm0);
                float p1 = __expf(sacc[nb][1] - nm0);
                float p2 = __expf(sacc[nb][2] - nm1);
                float p3 = __expf(sacc[nb][3] - nm1);
                sacc[nb][0] = p0; sacc[nb][1] = p1;
                sacc[nb][2] = p2; sacc[nb][3] = p3;
                rs0 += p0 + p1; rs1 += p2 + p3;
            }
            rs0 += __shfl_xor_sync(0xffffffffu, rs0, 1);
            rs0 += __shfl_xor_sync(0xffffffffu, rs0, 2);
            rs1 += __shfl_xor_sync(0xffffffffu, rs1, 1);
            rs1 += __shfl_xor_sync(0xffffffffu, rs1, 2);
            l0 = l0 * f0 + rs0;
            l1 = l1 * f1 + rs1;
            #pragma unroll
            for (int i = 0; i < 8; i++) {
                oacc[i][0] *= f0; oacc[i][1] *= f0;
                oacc[i][2] *= f1; oacc[i][3] *= f1;
            }
            // ---- O += P V, P 1-term fp16 ----
            #pragma unroll
            for (int kk = 0; kk < 4; kk++) {
                uint32_t ph[4];
                ph[0] = pack2h(sacc[2 * kk][0], sacc[2 * kk][1]);
                ph[1] = pack2h(sacc[2 * kk][2], sacc[2 * kk][3]);
                ph[2] = pack2h(sacc[2 * kk + 1][0], sacc[2 * kk + 1][1]);
                ph[3] = pack2h(sacc[2 * kk + 1][2], sacc[2 * kk + 1][3]);
                #pragma unroll
                for (int db2 = 0; db2 < 4; db2++) {
                    uint32_t vhreg[4];
                    uint32_t va = stg + FKTILE
                                  + (uint32_t)(kk * 16 * FSTR) + vboff
                                  + (uint32_t)(db2 * 32);
                    ldsm4t(vhreg, va);
                    mma16816h(oacc[db2 * 2 + 0], ph, vhreg[0], vhreg[1]);
                    mma16816h(oacc[db2 * 2 + 1], ph, vhreg[2], vhreg[3]);
                }
            }
        }
        __syncthreads();
    }

    const float inv0 = 1.0f / l0;
    const float inv1 = 1.0f / l1;
    const size_t tr0 = qrow0 + wm + r_lo;
    const size_t tr1 = tr0 + 8;
    #pragma unroll
    for (int db = 0; db < 8; db++) {
        const int col = hoff + db * 8 + cb;
        x[tr0 * CDIM + col]     += oacc[db][0] * inv0;
        x[tr0 * CDIM + col + 1] += oacc[db][1] * inv0;
        x[tr1 * CDIM + col]     += oacc[db][2] * inv1;
        x[tr1 * CDIM + col + 1] += oacc[db][3] * inv1;
    }
}

// ---------------------------------------------------------------------------
// Weight prep
// ---------------------------------------------------------------------------
__global__ __launch_bounds__(256) void transpose_f16_kernel(
    const float* __restrict__ W, __half* __restrict__ T, int K, int N,
    size_t src_lstride, size_t dst_lstride)
{
    __shared__ float ts[32][33];
    W += src_lstride * blockIdx.z;
    T += dst_lstride * blockIdx.z;
    const int n0 = blockIdx.x * 32, k0 = blockIdx.y * 32;
    const int tx = threadIdx.x & 31, ty = threadIdx.x >> 5;

    #pragma unroll
    for (int rr = 0; rr < 32; rr += 8)
        ts[ty + rr][tx] = W[(size_t)(k0 + ty + rr) * N + n0 + tx];
    __syncthreads();
    #pragma unroll
    for (int rr = 0; rr < 32; rr += 8)
        T[(size_t)(n0 + ty + rr) * K + k0 + tx] = __float2half_rn(ts[tx][ty + rr]);
}

__global__ __launch_bounds__(256) void transpose_qkv16_kernel(
    const float* __restrict__ wq, const float* __restrict__ wk,
    const float* __restrict__ wv, __half* __restrict__ T)
{
    __shared__ float ts[32][33];
    const int z = blockIdx.z;
    const int l = z / 3, sec = z % 3;
    const size_t CC = (size_t)CDIM * CDIM;
    const float* W = ((sec == 0) ? wq : (sec == 1) ? wk : wv) + (size_t)l * CC;
    __half* t = T + (size_t)l * 3 * CC + (size_t)sec * CC;
    const int n0 = blockIdx.x * 32, k0 = blockIdx.y * 32;
    const int tx = threadIdx.x & 31, ty = threadIdx.x >> 5;

    #pragma unroll
    for (int rr = 0; rr < 32; rr += 8)
        ts[ty + rr][tx] = W[(size_t)(k0 + ty + rr) * CDIM + n0 + tx];
    __syncthreads();
    #pragma unroll
    for (int rr = 0; rr < 32; rr += 8)
        t[(size_t)(n0 + ty + rr) * CDIM + k0 + tx] = __float2half_rn(ts[tx][ty + rr]);
}

// ---------------------------------------------------------------------------
// Embedding + QKV bias packing (fused)
// ---------------------------------------------------------------------------
#define EMBED_BLOCKS (BT * CDIM / 256)
#define PACK_BLOCKS  ((NLAYER * C3 + 255) / 256)

__global__ __launch_bounds__(256) void embed_pack_kernel(
    const int* __restrict__ idx, const float* __restrict__ tok,
    const float* __restrict__ pos, float* __restrict__ x,
    const float* __restrict__ bq, const float* __restrict__ bk,
    const float* __restrict__ bv, float* __restrict__ bqkv)
{
    if (blockIdx.x < EMBED_BLOCKS) {
        int i = blockIdx.x * 256 + threadIdx.x;
        int n = i >> 10;
        int c = i & (CDIM - 1);
        int t = n & (TLEN - 1);
        x[i] = tok[(size_t)idx[n] * CDIM + c] + pos[(size_t)t * CDIM + c];
    } else {
        int i = (blockIdx.x - EMBED_BLOCKS) * 256 + threadIdx.x;
        if (i < NLAYER * C3) {
            int l = i / C3, rem = i % C3, sec = rem >> 10, c = rem & 1023;
            const float* src = (sec == 0) ? bq : (sec == 1) ? bk : bv;
            bqkv[i] = src[l * CDIM + c];
        }
    }
}

// ---------------------------------------------------------------------------
// LayerNorm -> fp16 split pair
// ---------------------------------------------------------------------------
__global__ __launch_bounds__(256) void layernorm_split16_kernel(
    const float* __restrict__ x, const float* __restrict__ w,
    const float* __restrict__ b, __half* __restrict__ oh, __half* __restrict__ ol)
{
    __shared__ float2 sh[8];
    const size_t row = blockIdx.x;
    const int tid = threadIdx.x;
    const float* xr = x + row * CDIM;

    float4 v = *reinterpret_cast<const float4*>(&xr[tid * 4]);
    float s  = v.x + v.y + v.z + v.w;
    float ss = v.x * v.x + v.y * v.y + v.z * v.z + v.w * v.w;
    #pragma unroll
    for (int o = 16; o > 0; o >>= 1) {
        s  += __shfl_xor_sync(0xffffffffu, s,  o);
        ss += __shfl_xor_sync(0xffffffffu, ss, o);
    }
    if ((tid & 31) == 0) sh[tid >> 5] = make_float2(s, ss);
    __syncthreads();
    float ts = 0.f, tss = 0.f;
    #pragma unroll
    for (int i = 0; i < 8; i++) { ts += sh[i].x; tss += sh[i].y; }
    const float mu  = ts * (1.0f / CDIM);
    const float var = tss * (1.0f / CDIM) - mu * mu;
    const float rstd = rsqrtf(var + 1e-5f);

    float4 wv = *reinterpret_cast<const float4*>(&w[tid * 4]);
    float4 bv = *reinterpret_cast<const float4*>(&b[tid * 4]);
    float o0 = (v.x - mu) * rstd * wv.x + bv.x;
    float o1 = (v.y - mu) * rstd * wv.y + bv.y;
    float o2 = (v.z - mu) * rstd * wv.z + bv.z;
    float o3 = (v.w - mu) * rstd * wv.w + bv.w;
    uint32_t h0, l0p, h1, l1p;
    split2h(o0, o1, h0, l0p);
    split2h(o2, o3, h1, l1p);
    uint32_t* ohp = reinterpret_cast<uint32_t*>(oh + row * CDIM + tid * 4);
    uint32_t* olp = reinterpret_cast<uint32_t*>(ol + row * CDIM + tid * 4);
    ohp[0] = h0; ohp[1] = h1;
    olp[0] = l0p; olp[1] = l1p;
}

// ---------------------------------------------------------------------------
// Host orchestration
// ---------------------------------------------------------------------------
extern "C" void kernel_launch(void* const* d_in, const int* in_sizes, int n_in,
                              void* d_out, int out_size)
{
    const int*   idx     = (const int*)  d_in[0];
    const float* tok_emb = (const float*)d_in[1];
    const float* pos_emb = (const float*)d_in[2];
    const float* ln1_w   = (const float*)d_in[3];
    const float* ln1_b   = (const float*)d_in[4];
    const float* wq      = (const float*)d_in[5];
    const float* bq      = (const float*)d_in[6];
    const float* wk      = (const float*)d_in[7];
    const float* bk      = (const float*)d_in[8];
    const float* wv      = (const float*)d_in[9];
    const float* bv      = (const float*)d_in[10];
    const float* ln2_w   = (const float*)d_in[11];
    const float* ln2_b   = (const float*)d_in[12];
    const float* w1      = (const float*)d_in[13];
    const float* b1      = (const float*)d_in[14];
    const float* w2      = (const float*)d_in[15];
    const float* b2      = (const float*)d_in[16];
    const float* lnf_w   = (const float*)d_in[17];
    const float* lnf_b   = (const float*)d_in[18];
    const float* head_w  = (const float*)d_in[19];
    float* out = (float*)d_out;

    cudaFuncSetAttribute(hmma_gemm_h2<0, 0, 0>, cudaFuncAttributeMaxDynamicSharedMemorySize, GEMM64_SMEM);
    cudaFuncSetAttribute(hmma_gemm_h2<0, 1, 1>, cudaFuncAttributeMaxDynamicSharedMemorySize, GEMM64_SMEM);
    cudaFuncSetAttribute(hmma_gemm_h1<1, 1>, cudaFuncAttributeMaxDynamicSharedMemorySize, GEMM1_SMEM);
    cudaFuncSetAttribute(hmma_gemm_h1<0, 0>, cudaFuncAttributeMaxDynamicSharedMemorySize, GEMM1_SMEM);
    cudaFuncSetAttribute(flash_attn, cudaFuncAttributeMaxDynamicSharedMemorySize, FA_SMEM);

    float* x;
    cudaGetSymbolAddress((void**)&x, g_x);
    __half *ah, *al, *qkvh, *qkvl, *fh, *fl;
    cudaGetSymbolAddress((void**)&ah, g_ah);
    cudaGetSymbolAddress((void**)&al, g_al);
    cudaGetSymbolAddress((void**)&qkvh, g_qkvh);
    cudaGetSymbolAddress((void**)&qkvl, g_qkvl);
    cudaGetSymbolAddress((void**)&fh, g_fh);
    cudaGetSymbolAddress((void**)&fl, g_fl);
    __half *wqkv16, *w116, *w216, *hw16;
    float* bqkv;
    cudaGetSymbolAddress((void**)&wqkv16, g_wqkv16);
    cudaGetSymbolAddress((void**)&bqkv,   g_bqkv);
    cudaGetSymbolAddress((void**)&w116,  g_w116);
    cudaGetSymbolAddress((void**)&w216,  g_w216);
    cudaGetSymbolAddress((void**)&hw16,  g_hw16);

    transpose_qkv16_kernel<<<dim3(CDIM / 32, CDIM / 32, 3 * NLAYER), 256>>>(
        wq, wk, wv, wqkv16);
    embed_pack_kernel<<<EMBED_BLOCKS + PACK_BLOCKS, 256>>>(
        idx, tok_emb, pos_emb, x, bq, bk, bv, bqkv);
    layernorm_split16_kernel<<<BT, 256>>>(x, ln1_w, ln1_b, ah, al);
    hmma_gemm_h2<0, 1, 1><<<dim3(C3 / 128, BT / 128), 256, GEMM64_SMEM>>>(
        ah, al, wqkv16, bqkv, nullptr, nullptr, qkvh, qkvl, BT, C3, CDIM);
    transpose_f16_kernel<<<dim3(FDIM / 32, CDIM / 32, NLAYER), 256>>>(
        w1, w116, CDIM, FDIM, (size_t)CDIM * FDIM, (size_t)CDIM * FDIM);
    transpose_f16_kernel<<<dim3(CDIM / 32, FDIM / 32, NLAYER), 256>>>(
        w2, w216, FDIM, CDIM, (size_t)CDIM * FDIM, (size_t)CDIM * FDIM);
    transpose_f16_kernel<<<dim3(VDIM / 32, CDIM / 32, 1), 256>>>(
        head_w, hw16, CDIM, VDIM, 0, 0);

    const size_t CC = (size_t)CDIM * CDIM;
    for (int l = 0; l < NLAYER; l++) {
        const size_t oc  = (size_t)l * CDIM;
        const size_t o3  = (size_t)l * 3 * CC;
        const size_t of  = (size_t)l * FDIM;
        const size_t ocf = (size_t)l * CDIM * FDIM;

        if (l > 0) {
            layernorm_split16_kernel<<<BT, 256>>>(x, ln1_w + oc, ln1_b + oc, ah, al);
            hmma_gemm_h2<0, 1, 1><<<dim3(C3 / 128, BT / 128), 256, GEMM64_SMEM>>>(
                ah, al, wqkv16 + o3, bqkv + (size_t)l * C3, nullptr, nullptr,
                qkvh, qkvl, BT, C3, CDIM);
        }

        flash_attn<<<dim3(TLEN / 128, 2 * NH), 256, FA_SMEM>>>(qkvh, qkvl, x);

        layernorm_split16_kernel<<<BT, 256>>>(x, ln2_w + oc, ln2_b + oc, ah, al);
        hmma_gemm_h1<1, 1><<<dim3(FDIM / 128, BT / 128), 256, GEMM1_SMEM>>>(
            ah, w116 + ocf, b1 + of, nullptr, fh, fl, BT, FDIM, CDIM);
        hmma_gemm_h2<0, 0, 0><<<dim3(CDIM / 128, BT / 128), 256, GEMM64_SMEM>>>(
            fh, fl, w216 + ocf, b2 + oc, x, x, nullptr, nullptr, BT, CDIM, FDIM);
    }

    layernorm_split16_kernel<<<BT, 256>>>(x, lnf_w, lnf_b, ah, al);
    hmma_gemm_h1<0, 0><<<dim3(VDIM / 128, BT / 128), 256, GEMM1_SMEM>>>(
        ah, hw16, nullptr, out, nullptr, nullptr, BT, VDIM, CDIM);
}

// round 17
// speedup vs baseline: 1.8354x; 1.0423x over previous
#include <cuda_runtime.h>
#include <cuda_bf16.h>
#include <cuda_fp16.h>
#include <math.h>
#include <stdint.h>

// ---------------------------------------------------------------------------
// GPT forward: B=2, T=1024, C=1024, H=16, hd=64, F=4096, V=32000, L=8
// Q/FFN2: fp16 2-term. KV/FFN1/head: 1-term fp16.
// FA: Q 2-term, K/V 1-term, P 1-term. BK=64 interleaved mainloop.
// R17: QKV split into Q (2-term) + KV (1-term, hi-plane only).
// ---------------------------------------------------------------------------

#define BT 2048
#define CDIM 1024
#define FDIM 4096
#define VDIM 32000
#define NH 16
#define HD 64
#define TLEN 1024
#define NLAYER 8
#define C3 (3 * 1024)

typedef __nv_bfloat16 bf16;

// ------------------------- scratch ------------------------------------------
__device__ __align__(128) float g_x[BT * CDIM];
__device__ __align__(128) __half g_ah[BT * CDIM], g_al[BT * CDIM];
__device__ __align__(128) __half g_qkvh[BT * C3], g_qkvl[BT * C3];
__device__ __align__(128) __half g_fh[BT * FDIM], g_fl[BT * FDIM];
__device__ __align__(128) __half g_wqkv16[NLAYER * C3 * CDIM];
__device__ __align__(128) float g_bqkv[NLAYER * C3];
__device__ __align__(128) __half g_w116[NLAYER * CDIM * FDIM];
__device__ __align__(128) __half g_w216[NLAYER * FDIM * CDIM];
__device__ __align__(128) __half g_hw16[(size_t)VDIM * CDIM];

// ------------------------- PTX helpers --------------------------------------
__device__ __forceinline__ uint32_t smem_u32(const void* p) {
    uint32_t a;
    asm("{ .reg .u64 t; cvta.to.shared.u64 t, %1; cvt.u32.u64 %0, t; }"
        : "=r"(a) : "l"(p));
    return a;
}
__device__ __forceinline__ void cp16(uint32_t dst, const void* src) {
    asm volatile("cp.async.cg.shared.global [%0], [%1], 16;" :: "r"(dst), "l"(src));
}
__device__ __forceinline__ void cp_commit() {
    asm volatile("cp.async.commit_group;" ::: "memory");
}
__device__ __forceinline__ void cp_wait0() {
    asm volatile("cp.async.wait_group 0;" ::: "memory");
}
__device__ __forceinline__ void ldsm4(uint32_t (&r)[4], uint32_t a) {
    asm volatile("ldmatrix.sync.aligned.m8n8.x4.shared.b16 {%0,%1,%2,%3}, [%4];"
        : "=r"(r[0]), "=r"(r[1]), "=r"(r[2]), "=r"(r[3]) : "r"(a));
}
__device__ __forceinline__ void ldsm4t(uint32_t (&r)[4], uint32_t a) {
    asm volatile("ldmatrix.sync.aligned.m8n8.x4.trans.shared.b16 {%0,%1,%2,%3}, [%4];"
        : "=r"(r[0]), "=r"(r[1]), "=r"(r[2]), "=r"(r[3]) : "r"(a));
}
__device__ __forceinline__ void mma16816h(float (&c)[4], const uint32_t (&a)[4],
                                          uint32_t b0, uint32_t b1) {
    asm volatile("mma.sync.aligned.m16n8k16.row.col.f32.f16.f16.f32 "
        "{%0,%1,%2,%3}, {%4,%5,%6,%7}, {%8,%9}, {%0,%1,%2,%3};"
        : "+f"(c[0]), "+f"(c[1]), "+f"(c[2]), "+f"(c[3])
        : "r"(a[0]), "r"(a[1]), "r"(a[2]), "r"(a[3]), "r"(b0), "r"(b1));
}
__device__ __forceinline__ void split2h(float a, float b, uint32_t& hp, uint32_t& lp) {
    __half ha = __float2half_rn(a), hb = __float2half_rn(b);
    __half la = __float2half_rn(a - __half2float(ha));
    __half lb = __float2half_rn(b - __half2float(hb));
    hp = (uint32_t)__half_as_ushort(ha) | ((uint32_t)__half_as_ushort(hb) << 16);
    lp = (uint32_t)__half_as_ushort(la) | ((uint32_t)__half_as_ushort(lb) << 16);
}
__device__ __forceinline__ uint32_t pack2h(float a, float b) {
    __half ha = __float2half_rn(a), hb = __float2half_rn(b);
    return (uint32_t)__half_as_ushort(ha) | ((uint32_t)__half_as_ushort(hb) << 16);
}

#define TSTR64 144
#define TILE64 (128 * TSTR64)          // 18432
#define STAGE64 (3 * TILE64)           // 55296
#define GEMM64_SMEM (2 * STAGE64)      // 110592
#define STAGE1_B (2 * TILE64)          // 36864
#define GEMM1_SMEM (2 * STAGE1_B)      // 73728

// ---------------------------------------------------------------------------
// fp16 2-term 128x128 GEMM, BK=64: C = (Ah+Al)@Bh^T.  ldo = output row stride.
// ---------------------------------------------------------------------------
template<int GELU, int OSPLIT>
__global__ __launch_bounds__(256, 2) void hmma_gemm_h2(
    const __half* __restrict__ Ah, const __half* __restrict__ Al,
    const __half* __restrict__ Bh,
    const float* __restrict__ bias, const float* __restrict__ resid,
    float* __restrict__ C, __half* __restrict__ Oh, __half* __restrict__ Ol,
    int M, int N, int K, int ldo)
{
    extern __shared__ char sm[];
    const uint32_t sb = smem_u32(sm);
    const int tid = threadIdx.x;
    const int wid = tid >> 5;
    const int lid = tid & 31;
    const int bn = blockIdx.x * 128;
    const int bm = blockIdx.y * 128;
    const int wm = (wid & 3) * 32;
    const int wn = (wid >> 2) * 64;

    float acc[2][8][4];
    #pragma unroll
    for (int i = 0; i < 2; i++)
        #pragma unroll
        for (int j = 0; j < 8; j++)
            #pragma unroll
            for (int t = 0; t < 4; t++) acc[i][j][t] = 0.f;

    const uint32_t aoff = (uint32_t)((lid & 15) * TSTR64 + (lid >> 4) * 16);
    const uint32_t boff = (uint32_t)(((lid & 7) + (lid >> 4) * 8) * TSTR64
                                     + ((lid >> 3) & 1) * 16);
    const int nch = K >> 6;

    auto load_stage = [&](int ch, int s) {
        const int k0 = ch << 6;
        const uint32_t sbase = sb + s * STAGE64;
        #pragma unroll
        for (int u = 0; u < 4; u++) {
            int f = tid + u * 256;
            int r = f >> 3, c = f & 7;
            uint32_t so = (uint32_t)(r * TSTR64 + c * 16);
            size_t ga = (size_t)(bm + r) * K + k0 + c * 8;
            size_t gb = (size_t)(bn + r) * K + k0 + c * 8;
            cp16(sbase + 0 * TILE64 + so, Ah + ga);
            cp16(sbase + 1 * TILE64 + so, Al + ga);
            cp16(sbase + 2 * TILE64 + so, Bh + gb);
        }
    };

    load_stage(0, 0);
    cp_commit();

    for (int ch = 0; ch < nch; ch++) {
        const int s = ch & 1;
        cp_wait0();
        __syncthreads();
        if (ch + 1 < nch) {
            load_stage(ch + 1, s ^ 1);
            cp_commit();
        }

        const uint32_t stg = sb + s * STAGE64;
        #pragma unroll
        for (int ks = 0; ks < 4; ks++) {
            uint32_t ah_[2][4], al_[2][4];
            #pragma unroll
            for (int mb = 0; mb < 2; mb++) {
                uint32_t abase = stg + (uint32_t)((wm + mb * 16) * TSTR64)
                                 + aoff + ks * 32;
                ldsm4(ah_[mb], abase);
                ldsm4(al_[mb], abase + TILE64);
            }
            #pragma unroll
            for (int nb2 = 0; nb2 < 4; nb2++) {
                uint32_t bh_[4];
                uint32_t bbase = stg + 2 * TILE64
                                 + (uint32_t)((wn + nb2 * 16) * TSTR64)
                                 + boff + ks * 32;
                ldsm4(bh_, bbase);
                #pragma unroll
                for (int mb = 0; mb < 2; mb++) {
                    mma16816h(acc[mb][nb2 * 2 + 0], ah_[mb], bh_[0], bh_[1]);
                    mma16816h(acc[mb][nb2 * 2 + 1], ah_[mb], bh_[2], bh_[3]);
                    mma16816h(acc[mb][nb2 * 2 + 0], al_[mb], bh_[0], bh_[1]);
                    mma16816h(acc[mb][nb2 * 2 + 1], al_[mb], bh_[2], bh_[3]);
                }
            }
        }
    }

    const int er = bm + wm + (lid >> 2);
    const int ec = bn + wn + (lid & 3) * 2;
    #pragma unroll
    for (int mb = 0; mb < 2; mb++) {
        #pragma unroll
        for (int half = 0; half < 2; half++) {
            const int row = er + mb * 16 + half * 8;
            #pragma unroll
            for (int nb = 0; nb < 8; nb++) {
                const int col = ec + nb * 8;
                float v0 = acc[mb][nb][half * 2 + 0];
                float v1 = acc[mb][nb][half * 2 + 1];
                if (bias) { v0 += bias[col]; v1 += bias[col + 1]; }
                if (GELU) {
                    v0 = 0.5f * v0 * (1.0f + erff(v0 * 0.70710678118654752f));
                    v1 = 0.5f * v1 * (1.0f + erff(v1 * 0.70710678118654752f));
                }
                if (OSPLIT) {
                    uint32_t hp, lp;
                    split2h(v0, v1, hp, lp);
                    *reinterpret_cast<uint32_t*>(Oh + (size_t)row * ldo + col) = hp;
                    *reinterpret_cast<uint32_t*>(Ol + (size_t)row * ldo + col) = lp;
                } else {
                    if (resid) {
                        const float* rr = resid + (size_t)row * ldo;
                        v0 += rr[col]; v1 += rr[col + 1];
                    }
                    *reinterpret_cast<float2*>(C + (size_t)row * ldo + col) =
                        make_float2(v0, v1);
                }
            }
        }
    }
}

// ---------------------------------------------------------------------------
// fp16 1-term 128x128 GEMM, BK=64: C = Ah@Bh^T.
// OSPLIT=1: (+bias)(+GELU) -> Oh (and Ol if STOREL). OSPLIT=0: fp32 C.
// ---------------------------------------------------------------------------
template<int GELU, int OSPLIT, int STOREL>
__global__ __launch_bounds__(256, 2) void hmma_gemm_h1(
    const __half* __restrict__ Ah, const __half* __restrict__ Bh,
    const float* __restrict__ bias, float* __restrict__ C,
    __half* __restrict__ Oh, __half* __restrict__ Ol,
    int M, int N, int K, int ldo)
{
    extern __shared__ char sm[];
    const uint32_t sb = smem_u32(sm);
    const int tid = threadIdx.x;
    const int wid = tid >> 5;
    const int lid = tid & 31;
    const int bn = blockIdx.x * 128;
    const int bm = blockIdx.y * 128;
    const int wm = (wid & 3) * 32;
    const int wn = (wid >> 2) * 64;

    float acc[2][8][4];
    #pragma unroll
    for (int i = 0; i < 2; i++)
        #pragma unroll
        for (int j = 0; j < 8; j++)
            #pragma unroll
            for (int t = 0; t < 4; t++) acc[i][j][t] = 0.f;

    const uint32_t aoff = (uint32_t)((lid & 15) * TSTR64 + (lid >> 4) * 16);
    const uint32_t boff = (uint32_t)(((lid & 7) + (lid >> 4) * 8) * TSTR64
                                     + ((lid >> 3) & 1) * 16);
    const int nch = K >> 6;

    auto load_stage = [&](int ch, int s) {
        const int k0 = ch << 6;
        const uint32_t sbase = sb + s * STAGE1_B;
        #pragma unroll
        for (int u = 0; u < 4; u++) {
            int f = tid + u * 256;
            int r = f >> 3, c = f & 7;
            uint32_t so = (uint32_t)(r * TSTR64 + c * 16);
            size_t ga = (size_t)(bm + r) * K + k0 + c * 8;
            size_t gb = (size_t)(bn + r) * K + k0 + c * 8;
            cp16(sbase + 0 * TILE64 + so, Ah + ga);
            cp16(sbase + 1 * TILE64 + so, Bh + gb);
        }
    };

    load_stage(0, 0);
    cp_commit();

    for (int ch = 0; ch < nch; ch++) {
        const int s = ch & 1;
        cp_wait0();
        __syncthreads();
        if (ch + 1 < nch) {
            load_stage(ch + 1, s ^ 1);
            cp_commit();
        }

        const uint32_t stg = sb + s * STAGE1_B;
        #pragma unroll
        for (int ks = 0; ks < 4; ks++) {
            uint32_t ah_[2][4];
            #pragma unroll
            for (int mb = 0; mb < 2; mb++) {
                uint32_t abase = stg + (uint32_t)((wm + mb * 16) * TSTR64)
                                 + aoff + ks * 32;
                ldsm4(ah_[mb], abase);
            }
            #pragma unroll
            for (int nb2 = 0; nb2 < 4; nb2++) {
                uint32_t bh_[4];
                uint32_t bbase = stg + TILE64
                                 + (uint32_t)((wn + nb2 * 16) * TSTR64)
                                 + boff + ks * 32;
                ldsm4(bh_, bbase);
                #pragma unroll
                for (int mb = 0; mb < 2; mb++) {
                    mma16816h(acc[mb][nb2 * 2 + 0], ah_[mb], bh_[0], bh_[1]);
                    mma16816h(acc[mb][nb2 * 2 + 1], ah_[mb], bh_[2], bh_[3]);
                }
            }
        }
    }

    const int er = bm + wm + (lid >> 2);
    const int ec = bn + wn + (lid & 3) * 2;
    #pragma unroll
    for (int mb = 0; mb < 2; mb++) {
        #pragma unroll
        for (int half = 0; half < 2; half++) {
            const int row = er + mb * 16 + half * 8;
            #pragma unroll
            for (int nb = 0; nb < 8; nb++) {
                const int col = ec + nb * 8;
                float v0 = acc[mb][nb][half * 2 + 0];
                float v1 = acc[mb][nb][half * 2 + 1];
                if (bias) { v0 += bias[col]; v1 += bias[col + 1]; }
                if (GELU) {
                    v0 = 0.5f * v0 * (1.0f + erff(v0 * 0.70710678118654752f));
                    v1 = 0.5f * v1 * (1.0f + erff(v1 * 0.70710678118654752f));
                }
                if (OSPLIT) {
                    if (STOREL) {
                        uint32_t hp, lp;
                        split2h(v0, v1, hp, lp);
                        *reinterpret_cast<uint32_t*>(Oh + (size_t)row * ldo + col) = hp;
                        *reinterpret_cast<uint32_t*>(Ol + (size_t)row * ldo + col) = lp;
                    } else {
                        *reinterpret_cast<uint32_t*>(Oh + (size_t)row * ldo + col) =
                            pack2h(v0, v1);
                    }
                } else {
                    *reinterpret_cast<float2*>(C + (size_t)row * ldo + col) =
                        make_float2(v0, v1);
                }
            }
        }
    }
}

// ---------------------------------------------------------------------------
// Flash attention, fp16: Q 2-term, K/V 1-term, P 1-term. (unchanged from R16)
// ---------------------------------------------------------------------------
#define XSTR 3072
#define FSTR 144
#define FKTILE (64 * FSTR)
#define FA_STAGE (2 * FKTILE)
#define FA_SMEM  (2 * FA_STAGE)

__global__ __launch_bounds__(256) void flash_attn(
    const __half* __restrict__ qkvh, const __half* __restrict__ qkvl,
    float* __restrict__ x)
{
    extern __shared__ char sm[];
    const uint32_t sb = smem_u32(sm);
    const int tid = threadIdx.x;
    const int wid = tid >> 5;
    const int lid = tid & 31;
    const int qt = blockIdx.x;
    const int bh = blockIdx.y;
    const int b = bh >> 4, h = bh & 15;
    const size_t qrow0 = (size_t)b * TLEN + qt * 128;
    const size_t krow0 = (size_t)b * TLEN;
    const int hoff = h * HD;
    const int wm = wid * 16;

    auto load_kv = [&](int ssn, int s) {
        const size_t srow0 = krow0 + (size_t)ssn * 64;
        const uint32_t stb = sb + s * FA_STAGE;
        #pragma unroll
        for (int u = 0; u < 4; u++) {
            int f = tid + u * 256;
            int buf = f >> 9, r = (f >> 3) & 63, c = f & 7;
            int coloff = 1024 + (buf << 10) + hoff + c * 8;
            cp16(stb + buf * FKTILE + r * FSTR + c * 16,
                 qkvh + (srow0 + r) * XSTR + coloff);
        }
    };

    #pragma unroll
    for (int u = 0; u < 8; u++) {
        int f = tid + u * 256;
        int buf = f >> 10, r = (f >> 3) & 127, c = f & 7;
        const __half* src = buf ? qkvl : qkvh;
        cp16(sb + buf * 18432 + r * FSTR + c * 16,
             src + (qrow0 + r) * XSTR + hoff + c * 8);
    }
    cp_commit();
    cp_wait0();
    __syncthreads();

    uint32_t qfh[4][4], qfl[4][4];
    {
        uint32_t qaddr = sb + (uint32_t)((wm + (lid & 15)) * FSTR + (lid >> 4) * 16);
        #pragma unroll
        for (int ks = 0; ks < 4; ks++) {
            ldsm4(qfh[ks], qaddr + ks * 32);
            ldsm4(qfl[ks], qaddr + 18432 + ks * 32);
        }
    }
    __syncthreads();

    load_kv(0, 0);
    cp_commit();

    float oacc[8][4];
    #pragma unroll
    for (int i = 0; i < 8; i++)
        #pragma unroll
        for (int j = 0; j < 4; j++) oacc[i][j] = 0.f;
    float m0 = -1e30f, m1 = -1e30f, l0 = 0.f, l1 = 0.f;

    const int r_lo = lid >> 2;
    const int cb = (lid & 3) * 2;
    const uint32_t kboff = (uint32_t)(((lid & 7) + ((lid >> 4) << 3)) * FSTR
                                      + (((lid >> 3) & 1) << 4));
    const uint32_t vboff = (uint32_t)((((lid >> 3) & 1) * 8 + (lid & 7)) * FSTR
                                      + ((lid >> 4) << 4));
    const int ssmax = 2 * qt + 1;

    for (int ss = 0; ss <= ssmax; ss++) {
        const int s = ss & 1;
        cp_wait0();
        __syncthreads();
        if (ss < ssmax) {
            load_kv(ss + 1, s ^ 1);
            cp_commit();
        }

        const bool active = (ss * 64) <= (qt * 128 + wm + 15);
        if (active) {
            const uint32_t stg = sb + s * FA_STAGE;
            float sacc[8][4];
            #pragma unroll
            for (int i = 0; i < 8; i++)
                #pragma unroll
                for (int j = 0; j < 4; j++) sacc[i][j] = 0.f;
            #pragma unroll
            for (int nb2 = 0; nb2 < 4; nb2++) {
                #pragma unroll
                for (int ks = 0; ks < 4; ks++) {
                    uint32_t bhreg[4];
                    uint32_t a_ = stg + kboff + (uint32_t)(nb2 * 16 * FSTR) + ks * 32;
                    ldsm4(bhreg, a_);
                    mma16816h(sacc[nb2 * 2 + 0], qfh[ks], bhreg[0], bhreg[1]);
                    mma16816h(sacc[nb2 * 2 + 1], qfh[ks], bhreg[2], bhreg[3]);
                    mma16816h(sacc[nb2 * 2 + 0], qfl[ks], bhreg[0], bhreg[1]);
                    mma16816h(sacc[nb2 * 2 + 1], qfl[ks], bhreg[2], bhreg[3]);
                }
            }
            const int t0g = qt * 128 + wm + r_lo;
            #pragma unroll
            for (int nb = 0; nb < 8; nb++) {
                #pragma unroll
                for (int j = 0; j < 4; j++) {
                    float v = sacc[nb][j] * 0.125f;
                    int s_g = ss * 64 + nb * 8 + cb + (j & 1);
                    int t_g = t0g + (j >> 1) * 8;
                    sacc[nb][j] = (s_g > t_g) ? -1e30f : v;
                }
            }
            float mx0 = -1e30f, mx1 = -1e30f;
            #pragma unroll
            for (int nb = 0; nb < 8; nb++) {
                mx0 = fmaxf(mx0, fmaxf(sacc[nb][0], sacc[nb][1]));
                mx1 = fmaxf(mx1, fmaxf(sacc[nb][2], sacc[nb][3]));
            }
            mx0 = fmaxf(mx0, __shfl_xor_sync(0xffffffffu, mx0, 1));
            mx0 = fmaxf(mx0, __shfl_xor_sync(0xffffffffu, mx0, 2));
            mx1 = fmaxf(mx1, __shfl_xor_sync(0xffffffffu, mx1, 1));
            mx1 = fmaxf(mx1, __shfl_xor_sync(0xffffffffu, mx1, 2));
            float nm0 = fmaxf(m0, mx0), nm1 = fmaxf(m1, mx1);
            float f0 = __expf(m0 - nm0), f1 = __expf(m1 - nm1);
            m0 = nm0; m1 = nm1;
            float rs0 = 0.f, rs1 = 0.f;
            #pragma unroll
            for (int nb = 0; nb < 8; nb++) {
                float p0 = __expf(sacc[nb][0] - nm0);
                float p1 = __expf(sacc[nb][1] - nm0);
                float p2 = __expf(sacc[nb][2] - nm1);
                float p3 = __expf(sacc[nb][3] - nm1);
                sacc[nb][0] = p0; sacc[nb][1] = p1;
                sacc[nb][2] = p2; sacc[nb][3] = p3;
                rs0 += p0 + p1; rs1 += p2 + p3;
            }
            rs0 += __shfl_xor_sync(0xffffffffu, rs0, 1);
            rs0 += __shfl_xor_sync(0xffffffffu, rs0, 2);
            rs1 += __shfl_xor_sync(0xffffffffu, rs1, 1);
            rs1 += __shfl_xor_sync(0xffffffffu, rs1, 2);
            l0 = l0 * f0 + rs0;
            l1 = l1 * f1 + rs1;
            #pragma unroll
            for (int i = 0; i < 8; i++) {
                oacc[i][0] *= f0; oacc[i][1] *= f0;
                oacc[i][2] *= f1; oacc[i][3] *= f1;
            }
            #pragma unroll
            for (int kk = 0; kk < 4; kk++) {
                uint32_t ph[4];
                ph[0] = pack2h(sacc[2 * kk][0], sacc[2 * kk][1]);
                ph[1] = pack2h(sacc[2 * kk][2], sacc[2 * kk][3]);
                ph[2] = pack2h(sacc[2 * kk + 1][0], sacc[2 * kk + 1][1]);
                ph[3] = pack2h(sacc[2 * kk + 1][2], sacc[2 * kk + 1][3]);
                #pragma unroll
                for (int db2 = 0; db2 < 4; db2++) {
                    uint32_t vhreg[4];
                    uint32_t va = stg + FKTILE
                                  + (uint32_t)(kk * 16 * FSTR) + vboff
                                  + (uint32_t)(db2 * 32);
                    ldsm4t(vhreg, va);
                    mma16816h(oacc[db2 * 2 + 0], ph, vhreg[0], vhreg[1]);
                    mma16816h(oacc[db2 * 2 + 1], ph, vhreg[2], vhreg[3]);
                }
            }
        }
        __syncthreads();
    }

    const float inv0 = 1.0f / l0;
    const float inv1 = 1.0f / l1;
    const size_t tr0 = qrow0 + wm + r_lo;
    const size_t tr1 = tr0 + 8;
    #pragma unroll
    for (int db = 0; db < 8; db++) {
        const int col = hoff + db * 8 + cb;
        x[tr0 * CDIM + col]     += oacc[db][0] * inv0;
        x[tr0 * CDIM + col + 1] += oacc[db][1] * inv0;
        x[tr1 * CDIM + col]     += oacc[db][2] * inv1;
        x[tr1 * CDIM + col + 1] += oacc[db][3] * inv1;
    }
}

// ---------------------------------------------------------------------------
// Weight prep
// ---------------------------------------------------------------------------
__global__ __launch_bounds__(256) void transpose_f16_kernel(
    const float* __restrict__ W, __half* __restrict__ T, int K, int N,
    size_t src_lstride, size_t dst_lstride)
{
    __shared__ float ts[32][33];
    W += src_lstride * blockIdx.z;
    T += dst_lstride * blockIdx.z;
    const int n0 = blockIdx.x * 32, k0 = blockIdx.y * 32;
    const int tx = threadIdx.x & 31, ty = threadIdx.x >> 5;

    #pragma unroll
    for (int rr = 0; rr < 32; rr += 8)
        ts[ty + rr][tx] = W[(size_t)(k0 + ty + rr) * N + n0 + tx];
    __syncthreads();
    #pragma unroll
    for (int rr = 0; rr < 32; rr += 8)
        T[(size_t)(n0 + ty + rr) * K + k0 + tx] = __float2half_rn(ts[tx][ty + rr]);
}

__global__ __launch_bounds__(256) void transpose_qkv16_kernel(
    const float* __restrict__ wq, const float* __restrict__ wk,
    const float* __restrict__ wv, __half* __restrict__ T)
{
    __shared__ float ts[32][33];
    const int z = blockIdx.z;
    const int l = z / 3, sec = z % 3;
    const size_t CC = (size_t)CDIM * CDIM;
    const float* W = ((sec == 0) ? wq : (sec == 1) ? wk : wv) + (size_t)l * CC;
    __half* t = T + (size_t)l * 3 * CC + (size_t)sec * CC;
    const int n0 = blockIdx.x * 32, k0 = blockIdx.y * 32;
    const int tx = threadIdx.x & 31, ty = threadIdx.x >> 5;

    #pragma unroll
    for (int rr = 0; rr < 32; rr += 8)
        ts[ty + rr][tx] = W[(size_t)(k0 + ty + rr) * CDIM + n0 + tx];
    __syncthreads();
    #pragma unroll
    for (int rr = 0; rr < 32; rr += 8)
        t[(size_t)(n0 + ty + rr) * CDIM + k0 + tx] = __float2half_rn(ts[tx][ty + rr]);
}

// ---------------------------------------------------------------------------
// Embedding + QKV bias packing (fused)
// ---------------------------------------------------------------------------
#define EMBED_BLOCKS (BT * CDIM / 256)
#define PACK_BLOCKS  ((NLAYER * C3 + 255) / 256)

__global__ __launch_bounds__(256) void embed_pack_kernel(
    const int* __restrict__ idx, const float* __restrict__ tok,
    const float* __restrict__ pos, float* __restrict__ x,
    const float* __restrict__ bq, const float* __restrict__ bk,
    const float* __restrict__ bv, float* __restrict__ bqkv)
{
    if (blockIdx.x < EMBED_BLOCKS) {
        int i = blockIdx.x * 256 + threadIdx.x;
        int n = i >> 10;
        int c = i & (CDIM - 1);
        int t = n & (TLEN - 1);
        x[i] = tok[(size_t)idx[n] * CDIM + c] + pos[(size_t)t * CDIM + c];
    } else {
        int i = (blockIdx.x - EMBED_BLOCKS) * 256 + threadIdx.x;
        if (i < NLAYER * C3) {
            int l = i / C3, rem = i % C3, sec = rem >> 10, c = rem & 1023;
            const float* src = (sec == 0) ? bq : (sec == 1) ? bk : bv;
            bqkv[i] = src[l * CDIM + c];
        }
    }
}

// ---------------------------------------------------------------------------
// LayerNorm -> fp16 split pair
// ---------------------------------------------------------------------------
__global__ __launch_bounds__(256) void layernorm_split16_kernel(
    const float* __restrict__ x, const float* __restrict__ w,
    const float* __restrict__ b, __half* __restrict__ oh, __half* __restrict__ ol)
{
    __shared__ float2 sh[8];
    const size_t row = blockIdx.x;
    const int tid = threadIdx.x;
    const float* xr = x + row * CDIM;

    float4 v = *reinterpret_cast<const float4*>(&xr[tid * 4]);
    float s  = v.x + v.y + v.z + v.w;
    float ss = v.x * v.x + v.y * v.y + v.z * v.z + v.w * v.w;
    #pragma unroll
    for (int o = 16; o > 0; o >>= 1) {
        s  += __shfl_xor_sync(0xffffffffu, s,  o);
        ss += __shfl_xor_sync(0xffffffffu, ss, o);
    }
    if ((tid & 31) == 0) sh[tid >> 5] = make_float2(s, ss);
    __syncthreads();
    float ts = 0.f, tss = 0.f;
    #pragma unroll
    for (int i = 0; i < 8; i++) { ts += sh[i].x; tss += sh[i].y; }
    const float mu  = ts * (1.0f / CDIM);
    const float var = tss * (1.0f / CDIM) - mu * mu;
    const float rstd = rsqrtf(var + 1e-5f);

    float4 wv = *reinterpret_cast<const float4*>(&w[tid * 4]);
    float4 bv = *reinterpret_cast<const float4*>(&b[tid * 4]);
    float o0 = (v.x - mu) * rstd * wv.x + bv.x;
    float o1 = (v.y - mu) * rstd * wv.y + bv.y;
    float o2 = (v.z - mu) * rstd * wv.z + bv.z;
    float o3 = (v.w - mu) * rstd * wv.w + bv.w;
    uint32_t h0, l0p, h1, l1p;
    split2h(o0, o1, h0, l0p);
    split2h(o2, o3, h1, l1p);
    uint32_t* ohp = reinterpret_cast<uint32_t*>(oh + row * CDIM + tid * 4);
    uint32_t* olp = reinterpret_cast<uint32_t*>(ol + row * CDIM + tid * 4);
    ohp[0] = h0; ohp[1] = h1;
    olp[0] = l0p; olp[1] = l1p;
}

// ---------------------------------------------------------------------------
// Host orchestration
// ---------------------------------------------------------------------------
extern "C" void kernel_launch(void* const* d_in, const int* in_sizes, int n_in,
                              void* d_out, int out_size)
{
    const int*   idx     = (const int*)  d_in[0];
    const float* tok_emb = (const float*)d_in[1];
    const float* pos_emb = (const float*)d_in[2];
    const float* ln1_w   = (const float*)d_in[3];
    const float* ln1_b   = (const float*)d_in[4];
    const float* wq      = (const float*)d_in[5];
    const float* bq      = (const float*)d_in[6];
    const float* wk      = (const float*)d_in[7];
    const float* bk      = (const float*)d_in[8];
    const float* wv      = (const float*)d_in[9];
    const float* bv      = (const float*)d_in[10];
    const float* ln2_w   = (const float*)d_in[11];
    const float* ln2_b   = (const float*)d_in[12];
    const float* w1      = (const float*)d_in[13];
    const float* b1      = (const float*)d_in[14];
    const float* w2      = (const float*)d_in[15];
    const float* b2      = (const float*)d_in[16];
    const float* lnf_w   = (const float*)d_in[17];
    const float* lnf_b   = (const float*)d_in[18];
    const float* head_w  = (const float*)d_in[19];
    float* out = (float*)d_out;

    cudaFuncSetAttribute(hmma_gemm_h2<0, 0>, cudaFuncAttributeMaxDynamicSharedMemorySize, GEMM64_SMEM);
    cudaFuncSetAttribute(hmma_gemm_h2<0, 1>, cudaFuncAttributeMaxDynamicSharedMemorySize, GEMM64_SMEM);
    cudaFuncSetAttribute(hmma_gemm_h1<0, 1, 0>, cudaFuncAttributeMaxDynamicSharedMemorySize, GEMM1_SMEM);
    cudaFuncSetAttribute(hmma_gemm_h1<1, 1, 1>, cudaFuncAttributeMaxDynamicSharedMemorySize, GEMM1_SMEM);
    cudaFuncSetAttribute(hmma_gemm_h1<0, 0, 0>, cudaFuncAttributeMaxDynamicSharedMemorySize, GEMM1_SMEM);
    cudaFuncSetAttribute(flash_attn, cudaFuncAttributeMaxDynamicSharedMemorySize, FA_SMEM);

    float* x;
    cudaGetSymbolAddress((void**)&x, g_x);
    __half *ah, *al, *qkvh, *qkvl, *fh, *fl;
    cudaGetSymbolAddress((void**)&ah, g_ah);
    cudaGetSymbolAddress((void**)&al, g_al);
    cudaGetSymbolAddress((void**)&qkvh, g_qkvh);
    cudaGetSymbolAddress((void**)&qkvl, g_qkvl);
    cudaGetSymbolAddress((void**)&fh, g_fh);
    cudaGetSymbolAddress((void**)&fl, g_fl);
    __half *wqkv16, *w116, *w216, *hw16;
    float* bqkv;
    cudaGetSymbolAddress((void**)&wqkv16, g_wqkv16);
    cudaGetSymbolAddress((void**)&bqkv,   g_bqkv);
    cudaGetSymbolAddress((void**)&w116,  g_w116);
    cudaGetSymbolAddress((void**)&w216,  g_w216);
    cudaGetSymbolAddress((void**)&hw16,  g_hw16);

    transpose_qkv16_kernel<<<dim3(CDIM / 32, CDIM / 32, 3 * NLAYER), 256>>>(
        wq, wk, wv, wqkv16);
    embed_pack_kernel<<<EMBED_BLOCKS + PACK_BLOCKS, 256>>>(
        idx, tok_emb, pos_emb, x, bq, bk, bv, bqkv);
    transpose_f16_kernel<<<dim3(FDIM / 32, CDIM / 32, NLAYER), 256>>>(
        w1, w116, CDIM, FDIM, (size_t)CDIM * FDIM, (size_t)CDIM * FDIM);
    transpose_f16_kernel<<<dim3(CDIM / 32, FDIM / 32, NLAYER), 256>>>(
        w2, w216, FDIM, CDIM, (size_t)CDIM * FDIM, (size_t)CDIM * FDIM);
    transpose_f16_kernel<<<dim3(VDIM / 32, CDIM / 32, 1), 256>>>(
        head_w, hw16, CDIM, VDIM, 0, 0);

    const size_t CC = (size_t)CDIM * CDIM;
    for (int l = 0; l < NLAYER; l++) {
        const size_t oc  = (size_t)l * CDIM;
        const size_t o3  = (size_t)l * 3 * CC;
        const size_t of  = (size_t)l * FDIM;
        const size_t ocf = (size_t)l * CDIM * FDIM;

        layernorm_split16_kernel<<<BT, 256>>>(x, ln1_w + oc, ln1_b + oc, ah, al);
        // Q: 2-term, both planes, into cols [0,1024) of packed buffers
        hmma_gemm_h2<0, 1><<<dim3(CDIM / 128, BT / 128), 256, GEMM64_SMEM>>>(
            ah, al, wqkv16 + o3, bqkv + (size_t)l * C3, nullptr,
            nullptr, qkvh, qkvl, BT, CDIM, CDIM, C3);
        // KV: 1-term, hi plane only, into cols [1024,3072)
        hmma_gemm_h1<0, 1, 0><<<dim3(2 * CDIM / 128, BT / 128), 256, GEMM1_SMEM>>>(
            ah, wqkv16 + o3 + CC, bqkv + (size_t)l * C3 + CDIM, nullptr,
            qkvh + CDIM, nullptr, BT, 2 * CDIM, CDIM, C3);

        flash_attn<<<dim3(TLEN / 128, 2 * NH), 256, FA_SMEM>>>(qkvh, qkvl, x);

        layernorm_split16_kernel<<<BT, 256>>>(x, ln2_w + oc, ln2_b + oc, ah, al);
        hmma_gemm_h1<1, 1, 1><<<dim3(FDIM / 128, BT / 128), 256, GEMM1_SMEM>>>(
            ah, w116 + ocf, b1 + of, nullptr, fh, fl, BT, FDIM, CDIM, FDIM);
        hmma_gemm_h2<0, 0><<<dim3(CDIM / 128, BT / 128), 256, GEMM64_SMEM>>>(
            fh, fl, w216 + ocf, b2 + oc, x, x, nullptr, nullptr,
            BT, CDIM, FDIM, CDIM);
    }

    layernorm_split16_kernel<<<BT, 256>>>(x, lnf_w, lnf_b, ah, al);
    hmma_gemm_h1<0, 0, 0><<<dim3(VDIM / 128, BT / 128), 256, GEMM1_SMEM>>>(
        ah, hw16, nullptr, out, nullptr, nullptr, BT, VDIM, CDIM, VDIM);
}